// round 6
// baseline (speedup 1.0000x reference)
#include <cuda_runtime.h>
#include <cuda_fp16.h>
#include <cstdint>
#include <math.h>

// Problem constants: B=8, T=2048, D=1024, E=8 -> BT=16384
#define D_DIM 1024
#define E_DIM 8
#define BT_MAX 16384

__device__ float g_mix[BT_MAX * E_DIM];
__device__ __half g_xh[BT_MAX * D_DIM];            // 32 MB fp16 copy of x
__device__ __half g_wh[E_DIM * D_DIM * D_DIM];     // 16 MB fp16 copy of Wg

// ===========================================================================
// PTX helpers
// ===========================================================================
__device__ __forceinline__ uint32_t smem_u32(const void* p) {
    uint32_t a;
    asm("{ .reg .u64 t; cvta.to.shared.u64 t, %1; cvt.u32.u64 %0, t; }" : "=r"(a) : "l"(p));
    return a;
}

#define CP_ASYNC16(dst, src) \
    asm volatile("cp.async.cg.shared.global [%0], [%1], 16;" :: "r"(dst), "l"(src) : "memory")

__device__ __forceinline__ void ldmatrix_x4(uint32_t* r, uint32_t addr) {
    asm volatile("ldmatrix.sync.aligned.m8n8.x4.shared.b16 {%0,%1,%2,%3}, [%4];"
        : "=r"(r[0]), "=r"(r[1]), "=r"(r[2]), "=r"(r[3]) : "r"(addr));
}

__device__ __forceinline__ void mma16n8k16h(float* d, const uint32_t* a, const uint32_t* b) {
    asm volatile("mma.sync.aligned.m16n8k16.row.col.f32.f16.f16.f32 "
        "{%0,%1,%2,%3}, {%4,%5,%6,%7}, {%8,%9}, {%0,%1,%2,%3};"
        : "+f"(d[0]), "+f"(d[1]), "+f"(d[2]), "+f"(d[3])
        : "r"(a[0]), "r"(a[1]), "r"(a[2]), "r"(a[3]), "r"(b[0]), "r"(b[1]));
}

// ===========================================================================
// Kernel 0: fp32 -> fp16 conversion (grid-stride over float4)
// ===========================================================================
__global__ __launch_bounds__(256) void f2h_kernel(const float* __restrict__ src,
                                                  __half* __restrict__ dst, int n)
{
    int i = (blockIdx.x * 256 + threadIdx.x) * 4;
    if (i < n) {
        float4 v = *(const float4*)(src + i);
        __half2 h0 = __floats2half2_rn(v.x, v.y);
        __half2 h1 = __floats2half2_rn(v.z, v.w);
        uint2 u;
        u.x = *(uint32_t*)&h0;
        u.y = *(uint32_t*)&h1;
        *(uint2*)(dst + i) = u;
    }
}

// ===========================================================================
// Kernel 1: routing (verified; fp32)
// ===========================================================================
__global__ __launch_bounds__(128) void routing_kernel(
    const float* __restrict__ x,
    const float* __restrict__ Wf, const float* __restrict__ bf,
    const float* __restrict__ Wt, const float* __restrict__ bt,
    const float* __restrict__ alpha, int BT)
{
    int warp = blockIdx.x * (blockDim.x >> 5) + (threadIdx.x >> 5);
    int lane = threadIdx.x & 31;
    if (warp >= BT) return;

    const float* xr = x + (size_t)warp * D_DIM;
    float xv[32];
#pragma unroll
    for (int j = 0; j < 32; ++j) xv[j] = xr[lane + 32 * j];

    float dots[16];
#pragma unroll
    for (int r = 0; r < 16; ++r) {
        const float* w = (r < 8) ? (Wt + r * D_DIM) : (Wf + (r - 8) * D_DIM);
        float s = 0.0f;
#pragma unroll
        for (int j = 0; j < 32; ++j) s += xv[j] * w[lane + 32 * j];
#pragma unroll
        for (int off = 16; off > 0; off >>= 1)
            s += __shfl_xor_sync(0xffffffffu, s, off);
        dots[r] = s;
    }

    float tl[8], fl[8];
#pragma unroll
    for (int e = 0; e < 8; ++e) { tl[e] = dots[e] + bt[e]; fl[e] = dots[8 + e] + bf[e]; }

    float v0 = tl[0]; int i0 = 0;
    float v1 = -INFINITY; int i1 = -1;
#pragma unroll
    for (int e = 1; e < 8; ++e) {
        if (tl[e] > v0) { v1 = v0; i1 = i0; v0 = tl[e]; i0 = e; }
        else if (tl[e] > v1) { v1 = tl[e]; i1 = e; }
    }
    float p1 = expf(v1 - v0);
    float sv0 = 1.0f / (1.0f + p1);
    float sv1 = p1 * sv0;

    float mf = fl[0];
#pragma unroll
    for (int e = 1; e < 8; ++e) mf = fmaxf(mf, fl[e]);
    float ef[8]; float se = 0.0f;
#pragma unroll
    for (int e = 0; e < 8; ++e) { ef[e] = expf(fl[e] - mf); se += ef[e]; }
    float inv_se = 1.0f / se;

    float a = 1.0f / (1.0f + expf(-alpha[0]));
    float one_m_a = 1.0f - a;

#pragma unroll
    for (int e = 0; e < 8; ++e) {
        float tp = (e == i0) ? sv0 : ((e == i1) ? sv1 : 0.0f);
        float m = a * tp + one_m_a * ef[e] * inv_se;
        if (lane == e) g_mix[(size_t)warp * E_DIM + e] = m;
    }
}

// ===========================================================================
// Kernel 2: fp16 mma.sync fused MoE gate.
//   CTA tile 128x128, 8 warps (2m x 4n), warp tile 64x32, m16n8k16,
//   cp.async double-buffered BK=32, ldmatrix A frags, experts-outer with
//   register accOut fold: out[m,n] = sum_e sigmoid(z_e) * mix[m,e].
// ===========================================================================
#define F_BM 128
#define F_BN 128
#define F_BK 32
#define F_ST 40            // halves per smem row (32 + 8 pad) -> conflict-free
#define F_STAGE (F_BM * F_ST)   // 5120 halves per stage

__global__ __launch_bounds__(256, 1) void moe_gate_h(
    const float* __restrict__ bg,
    float* __restrict__ out)
{
    __shared__ __align__(16) __half As[2 * F_STAGE];
    __shared__ __align__(16) __half Bs[2 * F_STAGE];
    __shared__ __align__(16) float mixs[F_BM * E_DIM];

    const int tid = threadIdx.x;
    const int warp = tid >> 5, lane = tid & 31;
    const int wm = (warp & 1) * 64;
    const int wn = (warp >> 1) * 32;
    const int g = lane >> 2, tg = lane & 3;
    const int m0 = blockIdx.y * F_BM, n0 = blockIdx.x * F_BN;

    const uint32_t sAs = smem_u32(As);
    const uint32_t sBs = smem_u32(Bs);
    const __half* xh = g_xh;

    // stage mix tile: 128x8 floats = 256 float4
    ((float4*)mixs)[tid] = ((const float4*)(g_mix + (size_t)m0 * E_DIM))[tid];
    __syncthreads();

    float accOut[4][4][4];
#pragma unroll
    for (int a = 0; a < 4; ++a)
#pragma unroll
        for (int b = 0; b < 4; ++b)
#pragma unroll
            for (int c = 0; c < 4; ++c) accOut[a][b][c] = 0.0f;

    // A tile: 128 rows x 32 halves = 512 x 16B chunks; 2 per thread. Same for B.
#define H_LOAD_STAGE(st, k0, Bsrc) do {                                              \
    _Pragma("unroll")                                                                \
    for (int it = 0; it < 2; ++it) {                                                 \
        const int c = tid + it * 256;                                                \
        const int r = c >> 2, q = c & 3;                                             \
        CP_ASYNC16(sAs + (uint32_t)(((st) * F_STAGE + r * F_ST + q * 8) * 2),        \
                   xh + (size_t)(m0 + r) * D_DIM + (k0) + q * 8);                    \
        CP_ASYNC16(sBs + (uint32_t)(((st) * F_STAGE + r * F_ST + q * 8) * 2),        \
                   (Bsrc) + (size_t)r * D_DIM + (k0) + q * 8);                       \
    }                                                                                \
    asm volatile("cp.async.commit_group;" ::: "memory");                             \
} while (0)

    for (int e = 0; e < E_DIM; ++e) {
        const __half* Bsrc = g_wh + (size_t)e * D_DIM * D_DIM + (size_t)n0 * D_DIM;

        float acc[4][4][4];
#pragma unroll
        for (int a = 0; a < 4; ++a)
#pragma unroll
            for (int b = 0; b < 4; ++b)
#pragma unroll
                for (int c = 0; c < 4; ++c) acc[a][b][c] = 0.0f;

        H_LOAD_STAGE(0, 0, Bsrc);

        for (int ks = 0; ks < D_DIM / F_BK; ++ks) {
            const int cur = ks & 1;
            if (ks < D_DIM / F_BK - 1) {
                H_LOAD_STAGE(cur ^ 1, (ks + 1) * F_BK, Bsrc);
                asm volatile("cp.async.wait_group 1;" ::: "memory");
            } else {
                asm volatile("cp.async.wait_group 0;" ::: "memory");
            }
            __syncthreads();

            const uint32_t aStage = cur * F_STAGE;
            const __half* Bst = Bs + cur * F_STAGE;
#pragma unroll
            for (int kk = 0; kk < F_BK; kk += 16) {
                uint32_t afr[4][4], bfr[4][2];
#pragma unroll
                for (int mf = 0; mf < 4; ++mf) {
                    const uint32_t addr = sAs + 2u * (aStage
                        + (uint32_t)((wm + mf * 16 + (lane & 15)) * F_ST)
                        + (uint32_t)kk + (uint32_t)((lane >> 4) << 3));
                    ldmatrix_x4(afr[mf], addr);
                }
#pragma unroll
                for (int nf = 0; nf < 4; ++nf) {
                    const __half* bp = Bst + (wn + nf * 8 + g) * F_ST + kk + 2 * tg;
                    bfr[nf][0] = *(const uint32_t*)bp;
                    bfr[nf][1] = *(const uint32_t*)(bp + 8);
                }
#pragma unroll
                for (int mf = 0; mf < 4; ++mf)
#pragma unroll
                    for (int nf = 0; nf < 4; ++nf)
                        mma16n8k16h(acc[mf][nf], afr[mf], bfr[nf]);
            }
            __syncthreads();
        }

        // fold: accOut += mix[m,e] * sigmoid(acc + bg[e,n])
#pragma unroll
        for (int mf = 0; mf < 4; ++mf) {
            const int r = wm + mf * 16 + g;
            const float mx0 = mixs[r * E_DIM + e];
            const float mx1 = mixs[(r + 8) * E_DIM + e];
#pragma unroll
            for (int nf = 0; nf < 4; ++nf) {
                const int c = wn + nf * 8 + 2 * tg;
                const float b0 = __ldg(bg + (size_t)e * D_DIM + n0 + c);
                const float b1 = __ldg(bg + (size_t)e * D_DIM + n0 + c + 1);
                accOut[mf][nf][0] += mx0 / (1.0f + __expf(-(acc[mf][nf][0] + b0)));
                accOut[mf][nf][1] += mx0 / (1.0f + __expf(-(acc[mf][nf][1] + b1)));
                accOut[mf][nf][2] += mx1 / (1.0f + __expf(-(acc[mf][nf][2] + b0)));
                accOut[mf][nf][3] += mx1 / (1.0f + __expf(-(acc[mf][nf][3] + b1)));
            }
        }
    }

    // write 128x128 tile
#pragma unroll
    for (int mf = 0; mf < 4; ++mf) {
        const int r0 = m0 + wm + mf * 16 + g;
#pragma unroll
        for (int nf = 0; nf < 4; ++nf) {
            const int c = n0 + wn + nf * 8 + 2 * tg;
            *(float2*)(out + (size_t)r0 * D_DIM + c) =
                make_float2(accOut[mf][nf][0], accOut[mf][nf][1]);
            *(float2*)(out + (size_t)(r0 + 8) * D_DIM + c) =
                make_float2(accOut[mf][nf][2], accOut[mf][nf][3]);
        }
    }
}

// ===========================================================================
// Inputs: x, Wg, bg, Wf, bf, Wt, bt, alpha, num
// ===========================================================================
extern "C" void kernel_launch(void* const* d_in, const int* in_sizes, int n_in,
                              void* d_out, int out_size)
{
    const float* x     = (const float*)d_in[0];
    const float* Wg    = (const float*)d_in[1];
    const float* bg    = (const float*)d_in[2];
    const float* Wf    = (const float*)d_in[3];
    const float* bf    = (const float*)d_in[4];
    const float* Wt    = (const float*)d_in[5];
    const float* bt    = (const float*)d_in[6];
    const float* alpha = (const float*)d_in[7];
    float* out = (float*)d_out;

    const int BT = in_sizes[0] / D_DIM;   // 16384
    const int n_x = BT * D_DIM;           // 16777216
    const int n_w = E_DIM * D_DIM * D_DIM; // 8388608

    __half* xh_ptr = nullptr;
    __half* wh_ptr = nullptr;
    cudaGetSymbolAddress((void**)&xh_ptr, g_xh);
    cudaGetSymbolAddress((void**)&wh_ptr, g_wh);

    f2h_kernel<<<n_x / 1024, 256>>>(x, xh_ptr, n_x);
    f2h_kernel<<<n_w / 1024, 256>>>(Wg, wh_ptr, n_w);

    routing_kernel<<<(BT + 3) / 4, 128>>>(x, Wf, bf, Wt, bt, alpha, BT);

    dim3 grid(D_DIM / F_BN, BT / F_BM);   // (8, 128) = 1024 CTAs
    moe_gate_h<<<grid, 256>>>(bg, out);
}

// round 7
// speedup vs baseline: 1.0648x; 1.0648x over previous
#include <cuda_runtime.h>
#include <cuda_fp16.h>
#include <cstdint>
#include <math.h>

// Problem constants: B=8, T=2048, D=1024, E=8 -> BT=16384
#define D_DIM 1024
#define E_DIM 8
#define BT_MAX 16384

__device__ float g_mix[BT_MAX * E_DIM];
__device__ __half g_xh[BT_MAX * D_DIM];            // 32 MB fp16 copy of x
__device__ __half g_wh[E_DIM * D_DIM * D_DIM];     // 16 MB fp16 copy of Wg

// ===========================================================================
// PTX helpers
// ===========================================================================
__device__ __forceinline__ uint32_t smem_u32(const void* p) {
    uint32_t a;
    asm("{ .reg .u64 t; cvta.to.shared.u64 t, %1; cvt.u32.u64 %0, t; }" : "=r"(a) : "l"(p));
    return a;
}

#define CP_ASYNC16(dst, src) \
    asm volatile("cp.async.cg.shared.global [%0], [%1], 16;" :: "r"(dst), "l"(src) : "memory")

__device__ __forceinline__ void ldmatrix_x4(uint32_t* r, uint32_t addr) {
    asm volatile("ldmatrix.sync.aligned.m8n8.x4.shared.b16 {%0,%1,%2,%3}, [%4];"
        : "=r"(r[0]), "=r"(r[1]), "=r"(r[2]), "=r"(r[3]) : "r"(addr));
}

__device__ __forceinline__ void mma16n8k16h(float* d, const uint32_t* a, const uint32_t* b) {
    asm volatile("mma.sync.aligned.m16n8k16.row.col.f32.f16.f16.f32 "
        "{%0,%1,%2,%3}, {%4,%5,%6,%7}, {%8,%9}, {%0,%1,%2,%3};"
        : "+f"(d[0]), "+f"(d[1]), "+f"(d[2]), "+f"(d[3])
        : "r"(a[0]), "r"(a[1]), "r"(a[2]), "r"(a[3]), "r"(b[0]), "r"(b[1]));
}

// ===========================================================================
// Kernel 0: fp32 -> fp16 conversion
// ===========================================================================
__global__ __launch_bounds__(256) void f2h_kernel(const float* __restrict__ src,
                                                  __half* __restrict__ dst, int n)
{
    int i = (blockIdx.x * 256 + threadIdx.x) * 4;
    if (i < n) {
        float4 v = *(const float4*)(src + i);
        __half2 h0 = __floats2half2_rn(v.x, v.y);
        __half2 h1 = __floats2half2_rn(v.z, v.w);
        uint2 u;
        u.x = *(uint32_t*)&h0;
        u.y = *(uint32_t*)&h1;
        *(uint2*)(dst + i) = u;
    }
}

// ===========================================================================
// Kernel 1: routing (verified; fp32)
// ===========================================================================
__global__ __launch_bounds__(128) void routing_kernel(
    const float* __restrict__ x,
    const float* __restrict__ Wf, const float* __restrict__ bf,
    const float* __restrict__ Wt, const float* __restrict__ bt,
    const float* __restrict__ alpha, int BT)
{
    int warp = blockIdx.x * (blockDim.x >> 5) + (threadIdx.x >> 5);
    int lane = threadIdx.x & 31;
    if (warp >= BT) return;

    const float* xr = x + (size_t)warp * D_DIM;
    float xv[32];
#pragma unroll
    for (int j = 0; j < 32; ++j) xv[j] = xr[lane + 32 * j];

    float dots[16];
#pragma unroll
    for (int r = 0; r < 16; ++r) {
        const float* w = (r < 8) ? (Wt + r * D_DIM) : (Wf + (r - 8) * D_DIM);
        float s = 0.0f;
#pragma unroll
        for (int j = 0; j < 32; ++j) s += xv[j] * w[lane + 32 * j];
#pragma unroll
        for (int off = 16; off > 0; off >>= 1)
            s += __shfl_xor_sync(0xffffffffu, s, off);
        dots[r] = s;
    }

    float tl[8], fl[8];
#pragma unroll
    for (int e = 0; e < 8; ++e) { tl[e] = dots[e] + bt[e]; fl[e] = dots[8 + e] + bf[e]; }

    float v0 = tl[0]; int i0 = 0;
    float v1 = -INFINITY; int i1 = -1;
#pragma unroll
    for (int e = 1; e < 8; ++e) {
        if (tl[e] > v0) { v1 = v0; i1 = i0; v0 = tl[e]; i0 = e; }
        else if (tl[e] > v1) { v1 = tl[e]; i1 = e; }
    }
    float p1 = expf(v1 - v0);
    float sv0 = 1.0f / (1.0f + p1);
    float sv1 = p1 * sv0;

    float mf = fl[0];
#pragma unroll
    for (int e = 1; e < 8; ++e) mf = fmaxf(mf, fl[e]);
    float ef[8]; float se = 0.0f;
#pragma unroll
    for (int e = 0; e < 8; ++e) { ef[e] = expf(fl[e] - mf); se += ef[e]; }
    float inv_se = 1.0f / se;

    float a = 1.0f / (1.0f + expf(-alpha[0]));
    float one_m_a = 1.0f - a;

#pragma unroll
    for (int e = 0; e < 8; ++e) {
        float tp = (e == i0) ? sv0 : ((e == i1) ? sv1 : 0.0f);
        float m = a * tp + one_m_a * ef[e] * inv_se;
        if (lane == e) g_mix[(size_t)warp * E_DIM + e] = m;
    }
}

// ===========================================================================
// Kernel 2: fp16 mma.sync fused MoE gate, 4-stage flattened pipeline.
//   CTA tile 128x128, 8 warps (2m x 4n), warp tile 64x32, m16n8k16.
//   256 flat stages = 8 experts x 32 k-chunks; loads run continuously across
//   expert boundaries; sigmoid fold overlaps with in-flight loads.
// ===========================================================================
#define F_BM 128
#define F_BN 128
#define F_BK 32
#define F_ST 40                    // halves per smem row (32 + 8 pad)
#define F_STAGE (F_BM * F_ST)      // 5120 halves per stage
#define N_STAGES 4
#define N_FLAT (E_DIM * (D_DIM / F_BK))   // 256

// dynamic smem layout (bytes)
#define SMB_A    0                              // 4 * 10240 = 40960
#define SMB_B    (SMB_A + N_STAGES * F_STAGE * 2)   // 40960..81920
#define SMB_MIX  (SMB_B + N_STAGES * F_STAGE * 2)   // 81920, 4096 B
#define SMB_BGS  (SMB_MIX + F_BM * E_DIM * 4)       // 86016, 4096 B
#define SMEM_BYTES (SMB_BGS + E_DIM * F_BN * 4)     // 90112

__global__ __launch_bounds__(256, 1) void moe_gate_h(
    const float* __restrict__ bg,
    float* __restrict__ out)
{
    extern __shared__ char smc[];
    __half* As = (__half*)(smc + SMB_A);
    __half* Bs = (__half*)(smc + SMB_B);
    float* mixs = (float*)(smc + SMB_MIX);
    float* bgs  = (float*)(smc + SMB_BGS);

    const int tid = threadIdx.x;
    const int warp = tid >> 5, lane = tid & 31;
    const int wm = (warp & 1) * 64;
    const int wn = (warp >> 1) * 32;
    const int g = lane >> 2, tg = lane & 3;
    const int m0 = blockIdx.y * F_BM, n0 = blockIdx.x * F_BN;

    const uint32_t sAs = smem_u32(As);
    const uint32_t sBs = smem_u32(Bs);
    const __half* xh = g_xh;

    // preload mix tile (128x8 f32) and bg tiles (8x128 f32): 256 float4 each
    ((float4*)mixs)[tid] = ((const float4*)(g_mix + (size_t)m0 * E_DIM))[tid];
    {
        const int e = tid >> 5, c = (tid & 31) * 4;
        *(float4*)(bgs + e * F_BN + c) = *(const float4*)(bg + (size_t)e * D_DIM + n0 + c);
    }

    // issue one flat stage's loads (A 2 chunks + B 2 chunks per thread)
#define H_LOAD_STAGE(flat) do {                                                      \
    const int _buf = (flat) & (N_STAGES - 1);                                        \
    const int _e = (flat) >> 5;                                                      \
    const int _k0 = ((flat) & 31) * F_BK;                                            \
    const __half* _Bsrc = g_wh + (size_t)_e * D_DIM * D_DIM + (size_t)n0 * D_DIM;    \
    _Pragma("unroll")                                                                \
    for (int it = 0; it < 2; ++it) {                                                 \
        const int c = tid + it * 256;                                                \
        const int r = c >> 2, q = c & 3;                                             \
        CP_ASYNC16(sAs + (uint32_t)((_buf * F_STAGE + r * F_ST + q * 8) * 2),        \
                   xh + (size_t)(m0 + r) * D_DIM + _k0 + q * 8);                     \
        CP_ASYNC16(sBs + (uint32_t)((_buf * F_STAGE + r * F_ST + q * 8) * 2),        \
                   _Bsrc + (size_t)r * D_DIM + _k0 + q * 8);                         \
    }                                                                                \
} while (0)

    // prologue: stages 0..2
#pragma unroll
    for (int s = 0; s < N_STAGES - 1; ++s) {
        H_LOAD_STAGE(s);
        asm volatile("cp.async.commit_group;" ::: "memory");
    }

    float accOut[4][4][4];
#pragma unroll
    for (int a = 0; a < 4; ++a)
#pragma unroll
        for (int b = 0; b < 4; ++b)
#pragma unroll
            for (int c = 0; c < 4; ++c) accOut[a][b][c] = 0.0f;

    float acc[4][4][4];
#pragma unroll
    for (int a = 0; a < 4; ++a)
#pragma unroll
        for (int b = 0; b < 4; ++b)
#pragma unroll
            for (int c = 0; c < 4; ++c) acc[a][b][c] = 0.0f;

    for (int flat = 0; flat < N_FLAT; ++flat) {
        // stage `flat` resident once <=2 newer groups pending
        asm volatile("cp.async.wait_group 2;" ::: "memory");
        __syncthreads();

        // issue loads for stage flat+3 (buffer reuse is safe: all warps passed
        // the sync, so stage flat-1's reads are complete)
        if (flat + N_STAGES - 1 < N_FLAT)
            H_LOAD_STAGE(flat + N_STAGES - 1);
        asm volatile("cp.async.commit_group;" ::: "memory");

        // compute stage `flat`
        const uint32_t aStage = (uint32_t)(flat & (N_STAGES - 1)) * F_STAGE;
        const __half* Bst = Bs + (flat & (N_STAGES - 1)) * F_STAGE;
#pragma unroll
        for (int kk = 0; kk < F_BK; kk += 16) {
            uint32_t afr[4][4], bfr[4][2];
#pragma unroll
            for (int mf = 0; mf < 4; ++mf) {
                const uint32_t addr = sAs + 2u * (aStage
                    + (uint32_t)((wm + mf * 16 + (lane & 15)) * F_ST)
                    + (uint32_t)kk + (uint32_t)((lane >> 4) << 3));
                ldmatrix_x4(afr[mf], addr);
            }
#pragma unroll
            for (int nf = 0; nf < 4; ++nf) {
                const __half* bp = Bst + (wn + nf * 8 + g) * F_ST + kk + 2 * tg;
                bfr[nf][0] = *(const uint32_t*)bp;
                bfr[nf][1] = *(const uint32_t*)(bp + 8);
            }
#pragma unroll
            for (int mf = 0; mf < 4; ++mf)
#pragma unroll
                for (int nf = 0; nf < 4; ++nf)
                    mma16n8k16h(acc[mf][nf], afr[mf], bfr[nf]);
        }

        // expert boundary: fold into accOut, reset acc. Loads for the next
        // expert are already in flight; fold touches only regs + ro smem.
        if ((flat & 31) == 31) {
            const int e = flat >> 5;
#pragma unroll
            for (int mf = 0; mf < 4; ++mf) {
                const int r = wm + mf * 16 + g;
                const float mx0 = mixs[r * E_DIM + e];
                const float mx1 = mixs[(r + 8) * E_DIM + e];
#pragma unroll
                for (int nf = 0; nf < 4; ++nf) {
                    const int c = wn + nf * 8 + 2 * tg;
                    const float b0 = bgs[e * F_BN + c];
                    const float b1 = bgs[e * F_BN + c + 1];
                    accOut[mf][nf][0] += mx0 / (1.0f + __expf(-(acc[mf][nf][0] + b0)));
                    accOut[mf][nf][1] += mx0 / (1.0f + __expf(-(acc[mf][nf][1] + b1)));
                    accOut[mf][nf][2] += mx1 / (1.0f + __expf(-(acc[mf][nf][2] + b0)));
                    accOut[mf][nf][3] += mx1 / (1.0f + __expf(-(acc[mf][nf][3] + b1)));
                    acc[mf][nf][0] = 0.0f; acc[mf][nf][1] = 0.0f;
                    acc[mf][nf][2] = 0.0f; acc[mf][nf][3] = 0.0f;
                }
            }
        }
    }

    // write 128x128 tile
#pragma unroll
    for (int mf = 0; mf < 4; ++mf) {
        const int r0 = m0 + wm + mf * 16 + g;
#pragma unroll
        for (int nf = 0; nf < 4; ++nf) {
            const int c = n0 + wn + nf * 8 + 2 * tg;
            *(float2*)(out + (size_t)r0 * D_DIM + c) =
                make_float2(accOut[mf][nf][0], accOut[mf][nf][1]);
            *(float2*)(out + (size_t)(r0 + 8) * D_DIM + c) =
                make_float2(accOut[mf][nf][2], accOut[mf][nf][3]);
        }
    }
}

// ===========================================================================
// Inputs: x, Wg, bg, Wf, bf, Wt, bt, alpha, num
// ===========================================================================
extern "C" void kernel_launch(void* const* d_in, const int* in_sizes, int n_in,
                              void* d_out, int out_size)
{
    const float* x     = (const float*)d_in[0];
    const float* Wg    = (const float*)d_in[1];
    const float* bg    = (const float*)d_in[2];
    const float* Wf    = (const float*)d_in[3];
    const float* bf    = (const float*)d_in[4];
    const float* Wt    = (const float*)d_in[5];
    const float* bt    = (const float*)d_in[6];
    const float* alpha = (const float*)d_in[7];
    float* out = (float*)d_out;

    const int BT = in_sizes[0] / D_DIM;    // 16384
    const int n_x = BT * D_DIM;            // 16777216
    const int n_w = E_DIM * D_DIM * D_DIM; // 8388608

    __half* xh_ptr = nullptr;
    __half* wh_ptr = nullptr;
    cudaGetSymbolAddress((void**)&xh_ptr, g_xh);
    cudaGetSymbolAddress((void**)&wh_ptr, g_wh);

    cudaFuncSetAttribute(moe_gate_h,
                         cudaFuncAttributeMaxDynamicSharedMemorySize, SMEM_BYTES);

    f2h_kernel<<<n_x / 1024, 256>>>(x, xh_ptr, n_x);
    f2h_kernel<<<n_w / 1024, 256>>>(Wg, wh_ptr, n_w);

    routing_kernel<<<(BT + 3) / 4, 128>>>(x, Wf, bf, Wt, bt, alpha, BT);

    dim3 grid(D_DIM / F_BN, BT / F_BM);   // (8, 128) = 1024 CTAs
    moe_gate_h<<<grid, 256, SMEM_BYTES>>>(bg, out);
}

// round 8
// speedup vs baseline: 1.1747x; 1.1032x over previous
#include <cuda_runtime.h>
#include <cuda_fp16.h>
#include <cstdint>
#include <math.h>

// Problem constants: B=8, T=2048, D=1024, E=8 -> BT=16384
#define D_DIM 1024
#define E_DIM 8
#define BT_MAX 16384

__device__ float g_mix[BT_MAX * E_DIM];
__device__ __half g_xh[BT_MAX * D_DIM];            // 32 MB fp16 copy of x
__device__ __half g_wh[E_DIM * D_DIM * D_DIM];     // 16 MB fp16 copy of Wg

// ===========================================================================
// PTX helpers
// ===========================================================================
__device__ __forceinline__ uint32_t smem_u32(const void* p) {
    uint32_t a;
    asm("{ .reg .u64 t; cvta.to.shared.u64 t, %1; cvt.u32.u64 %0, t; }" : "=r"(a) : "l"(p));
    return a;
}

#define CP_ASYNC16(dst, src) \
    asm volatile("cp.async.cg.shared.global [%0], [%1], 16;" :: "r"(dst), "l"(src) : "memory")

__device__ __forceinline__ void ldmatrix_x4(uint32_t* r, uint32_t addr) {
    asm volatile("ldmatrix.sync.aligned.m8n8.x4.shared.b16 {%0,%1,%2,%3}, [%4];"
        : "=r"(r[0]), "=r"(r[1]), "=r"(r[2]), "=r"(r[3]) : "r"(addr));
}

__device__ __forceinline__ void mma16n8k16h(float* d, const uint32_t* a, const uint32_t* b) {
    asm volatile("mma.sync.aligned.m16n8k16.row.col.f32.f16.f16.f32 "
        "{%0,%1,%2,%3}, {%4,%5,%6,%7}, {%8,%9}, {%0,%1,%2,%3};"
        : "+f"(d[0]), "+f"(d[1]), "+f"(d[2]), "+f"(d[3])
        : "r"(a[0]), "r"(a[1]), "r"(a[2]), "r"(a[3]), "r"(b[0]), "r"(b[1]));
}

// ===========================================================================
// Kernel 0: fp32 -> fp16 conversion
// ===========================================================================
__global__ __launch_bounds__(256) void f2h_kernel(const float* __restrict__ src,
                                                  __half* __restrict__ dst, int n)
{
    int i = (blockIdx.x * 256 + threadIdx.x) * 4;
    if (i < n) {
        float4 v = *(const float4*)(src + i);
        __half2 h0 = __floats2half2_rn(v.x, v.y);
        __half2 h1 = __floats2half2_rn(v.z, v.w);
        uint2 u;
        u.x = *(uint32_t*)&h0;
        u.y = *(uint32_t*)&h1;
        *(uint2*)(dst + i) = u;
    }
}

// ===========================================================================
// Kernel 1: routing (verified; fp32)
// ===========================================================================
__global__ __launch_bounds__(128) void routing_kernel(
    const float* __restrict__ x,
    const float* __restrict__ Wf, const float* __restrict__ bf,
    const float* __restrict__ Wt, const float* __restrict__ bt,
    const float* __restrict__ alpha, int BT)
{
    int warp = blockIdx.x * (blockDim.x >> 5) + (threadIdx.x >> 5);
    int lane = threadIdx.x & 31;
    if (warp >= BT) return;

    const float* xr = x + (size_t)warp * D_DIM;
    float xv[32];
#pragma unroll
    for (int j = 0; j < 32; ++j) xv[j] = xr[lane + 32 * j];

    float dots[16];
#pragma unroll
    for (int r = 0; r < 16; ++r) {
        const float* w = (r < 8) ? (Wt + r * D_DIM) : (Wf + (r - 8) * D_DIM);
        float s = 0.0f;
#pragma unroll
        for (int j = 0; j < 32; ++j) s += xv[j] * w[lane + 32 * j];
#pragma unroll
        for (int off = 16; off > 0; off >>= 1)
            s += __shfl_xor_sync(0xffffffffu, s, off);
        dots[r] = s;
    }

    float tl[8], fl[8];
#pragma unroll
    for (int e = 0; e < 8; ++e) { tl[e] = dots[e] + bt[e]; fl[e] = dots[8 + e] + bf[e]; }

    float v0 = tl[0]; int i0 = 0;
    float v1 = -INFINITY; int i1 = -1;
#pragma unroll
    for (int e = 1; e < 8; ++e) {
        if (tl[e] > v0) { v1 = v0; i1 = i0; v0 = tl[e]; i0 = e; }
        else if (tl[e] > v1) { v1 = tl[e]; i1 = e; }
    }
    float p1 = expf(v1 - v0);
    float sv0 = 1.0f / (1.0f + p1);
    float sv1 = p1 * sv0;

    float mf = fl[0];
#pragma unroll
    for (int e = 1; e < 8; ++e) mf = fmaxf(mf, fl[e]);
    float ef[8]; float se = 0.0f;
#pragma unroll
    for (int e = 0; e < 8; ++e) { ef[e] = expf(fl[e] - mf); se += ef[e]; }
    float inv_se = 1.0f / se;

    float a = 1.0f / (1.0f + expf(-alpha[0]));
    float one_m_a = 1.0f - a;

#pragma unroll
    for (int e = 0; e < 8; ++e) {
        float tp = (e == i0) ? sv0 : ((e == i1) ? sv1 : 0.0f);
        float m = a * tp + one_m_a * ef[e] * inv_se;
        if (lane == e) g_mix[(size_t)warp * E_DIM + e] = m;
    }
}

// ===========================================================================
// Kernel 2: fp16 mma.sync fused MoE gate, 512 threads (16 warps).
//   CTA tile 128x128, warp grid 4m x 4n, warp tile 32x32 (mf 2, nf 4),
//   m16n8k16, 4-stage cp.async, flattened 256-stage expert loop.
// ===========================================================================
#define F_BM 128
#define F_BN 128
#define F_BK 32
#define F_ST 40                    // halves per smem row (32 + 8 pad)
#define F_STAGE (F_BM * F_ST)      // 5120 halves per stage
#define N_STAGES 4
#define N_FLAT (E_DIM * (D_DIM / F_BK))   // 256
#define N_THREADS 512

// dynamic smem layout (bytes)
#define SMB_A    0                                  // 4 * 10240 = 40960
#define SMB_B    (SMB_A + N_STAGES * F_STAGE * 2)   // 40960..81920
#define SMB_MIX  (SMB_B + N_STAGES * F_STAGE * 2)   // 81920, 4096 B
#define SMB_BGS  (SMB_MIX + F_BM * E_DIM * 4)       // 86016, 4096 B
#define SMEM_BYTES (SMB_BGS + E_DIM * F_BN * 4)     // 90112

__global__ __launch_bounds__(N_THREADS, 1) void moe_gate_h(
    const float* __restrict__ bg,
    float* __restrict__ out)
{
    extern __shared__ char smc[];
    __half* As = (__half*)(smc + SMB_A);
    __half* Bs = (__half*)(smc + SMB_B);
    float* mixs = (float*)(smc + SMB_MIX);
    float* bgs  = (float*)(smc + SMB_BGS);

    const int tid = threadIdx.x;
    const int warp = tid >> 5, lane = tid & 31;
    const int wm = (warp & 3) * 32;       // 4 m-warps
    const int wn = (warp >> 2) * 32;      // 4 n-warps
    const int g = lane >> 2, tg = lane & 3;
    const int m0 = blockIdx.y * F_BM, n0 = blockIdx.x * F_BN;

    const uint32_t sAs = smem_u32(As);
    const uint32_t sBs = smem_u32(Bs);
    const __half* xh = g_xh;

    // preload mix tile (128x8 f32 = 256 float4) and bg tiles (8x128 f32 = 256 float4)
    if (tid < 256) {
        ((float4*)mixs)[tid] = ((const float4*)(g_mix + (size_t)m0 * E_DIM))[tid];
    } else {
        const int t2 = tid - 256;
        const int e = t2 >> 5, c = (t2 & 31) * 4;
        *(float4*)(bgs + e * F_BN + c) = *(const float4*)(bg + (size_t)e * D_DIM + n0 + c);
    }

    // one flat stage's loads: A 1 chunk + B 1 chunk per thread (512 chunks each)
#define H_LOAD_STAGE(flat) do {                                                      \
    const int _buf = (flat) & (N_STAGES - 1);                                        \
    const int _e = (flat) >> 5;                                                      \
    const int _k0 = ((flat) & 31) * F_BK;                                            \
    const __half* _Bsrc = g_wh + (size_t)_e * D_DIM * D_DIM + (size_t)n0 * D_DIM;    \
    const int _r = tid >> 2, _q = tid & 3;                                           \
    CP_ASYNC16(sAs + (uint32_t)((_buf * F_STAGE + _r * F_ST + _q * 8) * 2),          \
               xh + (size_t)(m0 + _r) * D_DIM + _k0 + _q * 8);                       \
    CP_ASYNC16(sBs + (uint32_t)((_buf * F_STAGE + _r * F_ST + _q * 8) * 2),          \
               _Bsrc + (size_t)_r * D_DIM + _k0 + _q * 8);                           \
} while (0)

    // prologue: stages 0..2
#pragma unroll
    for (int s = 0; s < N_STAGES - 1; ++s) {
        H_LOAD_STAGE(s);
        asm volatile("cp.async.commit_group;" ::: "memory");
    }

    float accOut[2][4][4];
#pragma unroll
    for (int a = 0; a < 2; ++a)
#pragma unroll
        for (int b = 0; b < 4; ++b)
#pragma unroll
            for (int c = 0; c < 4; ++c) accOut[a][b][c] = 0.0f;

    float acc[2][4][4];
#pragma unroll
    for (int a = 0; a < 2; ++a)
#pragma unroll
        for (int b = 0; b < 4; ++b)
#pragma unroll
            for (int c = 0; c < 4; ++c) acc[a][b][c] = 0.0f;

    for (int flat = 0; flat < N_FLAT; ++flat) {
        asm volatile("cp.async.wait_group 2;" ::: "memory");
        __syncthreads();

        if (flat + N_STAGES - 1 < N_FLAT)
            H_LOAD_STAGE(flat + N_STAGES - 1);
        asm volatile("cp.async.commit_group;" ::: "memory");

        const uint32_t aStage = (uint32_t)(flat & (N_STAGES - 1)) * F_STAGE;
        const __half* Bst = Bs + (flat & (N_STAGES - 1)) * F_STAGE;
#pragma unroll
        for (int kk = 0; kk < F_BK; kk += 16) {
            uint32_t afr[2][4], bfr[4][2];
#pragma unroll
            for (int mf = 0; mf < 2; ++mf) {
                const uint32_t addr = sAs + 2u * (aStage
                    + (uint32_t)((wm + mf * 16 + (lane & 15)) * F_ST)
                    + (uint32_t)kk + (uint32_t)((lane >> 4) << 3));
                ldmatrix_x4(afr[mf], addr);
            }
#pragma unroll
            for (int nf = 0; nf < 4; ++nf) {
                const __half* bp = Bst + (wn + nf * 8 + g) * F_ST + kk + 2 * tg;
                bfr[nf][0] = *(const uint32_t*)bp;
                bfr[nf][1] = *(const uint32_t*)(bp + 8);
            }
#pragma unroll
            for (int mf = 0; mf < 2; ++mf)
#pragma unroll
                for (int nf = 0; nf < 4; ++nf)
                    mma16n8k16h(acc[mf][nf], afr[mf], bfr[nf]);
        }

        // expert boundary: fold into accOut, reset acc
        if ((flat & 31) == 31) {
            const int e = flat >> 5;
#pragma unroll
            for (int mf = 0; mf < 2; ++mf) {
                const int r = wm + mf * 16 + g;
                const float mx0 = mixs[r * E_DIM + e];
                const float mx1 = mixs[(r + 8) * E_DIM + e];
#pragma unroll
                for (int nf = 0; nf < 4; ++nf) {
                    const int c = wn + nf * 8 + 2 * tg;
                    const float b0 = bgs[e * F_BN + c];
                    const float b1 = bgs[e * F_BN + c + 1];
                    accOut[mf][nf][0] += mx0 / (1.0f + __expf(-(acc[mf][nf][0] + b0)));
                    accOut[mf][nf][1] += mx0 / (1.0f + __expf(-(acc[mf][nf][1] + b1)));
                    accOut[mf][nf][2] += mx1 / (1.0f + __expf(-(acc[mf][nf][2] + b0)));
                    accOut[mf][nf][3] += mx1 / (1.0f + __expf(-(acc[mf][nf][3] + b1)));
                    acc[mf][nf][0] = 0.0f; acc[mf][nf][1] = 0.0f;
                    acc[mf][nf][2] = 0.0f; acc[mf][nf][3] = 0.0f;
                }
            }
        }
    }

    // write 128x128 tile (each warp: 32 rows x 32 cols)
#pragma unroll
    for (int mf = 0; mf < 2; ++mf) {
        const int r0 = m0 + wm + mf * 16 + g;
#pragma unroll
        for (int nf = 0; nf < 4; ++nf) {
            const int c = n0 + wn + nf * 8 + 2 * tg;
            *(float2*)(out + (size_t)r0 * D_DIM + c) =
                make_float2(accOut[mf][nf][0], accOut[mf][nf][1]);
            *(float2*)(out + (size_t)(r0 + 8) * D_DIM + c) =
                make_float2(accOut[mf][nf][2], accOut[mf][nf][3]);
        }
    }
}

// ===========================================================================
// Inputs: x, Wg, bg, Wf, bf, Wt, bt, alpha, num
// ===========================================================================
extern "C" void kernel_launch(void* const* d_in, const int* in_sizes, int n_in,
                              void* d_out, int out_size)
{
    const float* x     = (const float*)d_in[0];
    const float* Wg    = (const float*)d_in[1];
    const float* bg    = (const float*)d_in[2];
    const float* Wf    = (const float*)d_in[3];
    const float* bf    = (const float*)d_in[4];
    const float* Wt    = (const float*)d_in[5];
    const float* bt    = (const float*)d_in[6];
    const float* alpha = (const float*)d_in[7];
    float* out = (float*)d_out;

    const int BT = in_sizes[0] / D_DIM;    // 16384
    const int n_x = BT * D_DIM;            // 16777216
    const int n_w = E_DIM * D_DIM * D_DIM; // 8388608

    __half* xh_ptr = nullptr;
    __half* wh_ptr = nullptr;
    cudaGetSymbolAddress((void**)&xh_ptr, g_xh);
    cudaGetSymbolAddress((void**)&wh_ptr, g_wh);

    cudaFuncSetAttribute(moe_gate_h,
                         cudaFuncAttributeMaxDynamicSharedMemorySize, SMEM_BYTES);

    f2h_kernel<<<n_x / 1024, 256>>>(x, xh_ptr, n_x);
    f2h_kernel<<<n_w / 1024, 256>>>(Wg, wh_ptr, n_w);

    routing_kernel<<<(BT + 3) / 4, 128>>>(x, Wf, bf, Wt, bt, alpha, BT);

    dim3 grid(D_DIM / F_BN, BT / F_BM);   // (8, 128) = 1024 CTAs
    moe_gate_h<<<grid, N_THREADS, SMEM_BYTES>>>(bg, out);
}

// round 9
// speedup vs baseline: 1.3349x; 1.1363x over previous
#include <cuda_runtime.h>
#include <cuda_fp16.h>
#include <cstdint>
#include <math.h>

// Problem constants: B=8, T=2048, D=1024, E=8 -> BT=16384
#define D_DIM 1024
#define E_DIM 8
#define BT_MAX 16384

__device__ float g_mix[BT_MAX * E_DIM];
__device__ __half g_xh[BT_MAX * D_DIM];            // 32 MB fp16 copy of x
__device__ __half g_wh[E_DIM * D_DIM * D_DIM];     // 16 MB fp16 copy of Wg

// ===========================================================================
// PTX helpers
// ===========================================================================
__device__ __forceinline__ uint32_t smem_u32(const void* p) {
    uint32_t a;
    asm("{ .reg .u64 t; cvta.to.shared.u64 t, %1; cvt.u32.u64 %0, t; }" : "=r"(a) : "l"(p));
    return a;
}

#define CP_ASYNC16(dst, src) \
    asm volatile("cp.async.cg.shared.global [%0], [%1], 16;" :: "r"(dst), "l"(src) : "memory")

__device__ __forceinline__ void ldmatrix_x4(uint32_t* r, uint32_t addr) {
    asm volatile("ldmatrix.sync.aligned.m8n8.x4.shared.b16 {%0,%1,%2,%3}, [%4];"
        : "=r"(r[0]), "=r"(r[1]), "=r"(r[2]), "=r"(r[3]) : "r"(addr));
}

__device__ __forceinline__ void mma16n8k16h(float* d, const uint32_t* a, const uint32_t* b) {
    asm volatile("mma.sync.aligned.m16n8k16.row.col.f32.f16.f16.f32 "
        "{%0,%1,%2,%3}, {%4,%5,%6,%7}, {%8,%9}, {%0,%1,%2,%3};"
        : "+f"(d[0]), "+f"(d[1]), "+f"(d[2]), "+f"(d[3])
        : "r"(a[0]), "r"(a[1]), "r"(a[2]), "r"(a[3]), "r"(b[0]), "r"(b[1]));
}

// ===========================================================================
// Kernel 0: fp32 -> fp16 conversion
// ===========================================================================
__global__ __launch_bounds__(256) void f2h_kernel(const float* __restrict__ src,
                                                  __half* __restrict__ dst, int n)
{
    int i = (blockIdx.x * 256 + threadIdx.x) * 4;
    if (i < n) {
        float4 v = *(const float4*)(src + i);
        __half2 h0 = __floats2half2_rn(v.x, v.y);
        __half2 h1 = __floats2half2_rn(v.z, v.w);
        uint2 u;
        u.x = *(uint32_t*)&h0;
        u.y = *(uint32_t*)&h1;
        *(uint2*)(dst + i) = u;
    }
}

// ===========================================================================
// Kernel 1: routing (verified; fp32)
// ===========================================================================
__global__ __launch_bounds__(128) void routing_kernel(
    const float* __restrict__ x,
    const float* __restrict__ Wf, const float* __restrict__ bf,
    const float* __restrict__ Wt, const float* __restrict__ bt,
    const float* __restrict__ alpha, int BT)
{
    int warp = blockIdx.x * (blockDim.x >> 5) + (threadIdx.x >> 5);
    int lane = threadIdx.x & 31;
    if (warp >= BT) return;

    const float* xr = x + (size_t)warp * D_DIM;
    float xv[32];
#pragma unroll
    for (int j = 0; j < 32; ++j) xv[j] = xr[lane + 32 * j];

    float dots[16];
#pragma unroll
    for (int r = 0; r < 16; ++r) {
        const float* w = (r < 8) ? (Wt + r * D_DIM) : (Wf + (r - 8) * D_DIM);
        float s = 0.0f;
#pragma unroll
        for (int j = 0; j < 32; ++j) s += xv[j] * w[lane + 32 * j];
#pragma unroll
        for (int off = 16; off > 0; off >>= 1)
            s += __shfl_xor_sync(0xffffffffu, s, off);
        dots[r] = s;
    }

    float tl[8], fl[8];
#pragma unroll
    for (int e = 0; e < 8; ++e) { tl[e] = dots[e] + bt[e]; fl[e] = dots[8 + e] + bf[e]; }

    float v0 = tl[0]; int i0 = 0;
    float v1 = -INFINITY; int i1 = -1;
#pragma unroll
    for (int e = 1; e < 8; ++e) {
        if (tl[e] > v0) { v1 = v0; i1 = i0; v0 = tl[e]; i0 = e; }
        else if (tl[e] > v1) { v1 = tl[e]; i1 = e; }
    }
    float p1 = expf(v1 - v0);
    float sv0 = 1.0f / (1.0f + p1);
    float sv1 = p1 * sv0;

    float mf = fl[0];
#pragma unroll
    for (int e = 1; e < 8; ++e) mf = fmaxf(mf, fl[e]);
    float ef[8]; float se = 0.0f;
#pragma unroll
    for (int e = 0; e < 8; ++e) { ef[e] = expf(fl[e] - mf); se += ef[e]; }
    float inv_se = 1.0f / se;

    float a = 1.0f / (1.0f + expf(-alpha[0]));
    float one_m_a = 1.0f - a;

#pragma unroll
    for (int e = 0; e < 8; ++e) {
        float tp = (e == i0) ? sv0 : ((e == i1) ? sv1 : 0.0f);
        float m = a * tp + one_m_a * ef[e] * inv_se;
        if (lane == e) g_mix[(size_t)warp * E_DIM + e] = m;
    }
}

// ===========================================================================
// Kernel 2: fp16 mma.sync fused MoE gate, 512 threads (16 warps).
//   CTA tile 128x128, warp grid 4m x 4n, warp tile 32x32, m16n8k16,
//   ALL fragments via ldmatrix.x4; 4-stage cp.async; flattened expert loop.
// ===========================================================================
#define F_BM 128
#define F_BN 128
#define F_BK 32
#define F_ST 40                    // halves per smem row (32 + 8 pad)
#define F_STAGE (F_BM * F_ST)      // 5120 halves per stage
#define N_STAGES 4
#define N_FLAT (E_DIM * (D_DIM / F_BK))   // 256
#define N_THREADS 512

// dynamic smem layout (bytes)
#define SMB_A    0                                  // 4 * 10240 = 40960
#define SMB_B    (SMB_A + N_STAGES * F_STAGE * 2)   // 40960..81920
#define SMB_MIX  (SMB_B + N_STAGES * F_STAGE * 2)   // 81920, 4096 B
#define SMB_BGS  (SMB_MIX + F_BM * E_DIM * 4)       // 86016, 4096 B
#define SMEM_BYTES (SMB_BGS + E_DIM * F_BN * 4)     // 90112

__global__ __launch_bounds__(N_THREADS, 1) void moe_gate_h(
    const float* __restrict__ bg,
    float* __restrict__ out)
{
    extern __shared__ char smc[];
    __half* As = (__half*)(smc + SMB_A);
    __half* Bs = (__half*)(smc + SMB_B);
    float* mixs = (float*)(smc + SMB_MIX);
    float* bgs  = (float*)(smc + SMB_BGS);

    const int tid = threadIdx.x;
    const int warp = tid >> 5, lane = tid & 31;
    const int wm = (warp & 3) * 32;       // 4 m-warps
    const int wn = (warp >> 2) * 32;      // 4 n-warps
    const int g = lane >> 2, tg = lane & 3;
    const int m0 = blockIdx.y * F_BM, n0 = blockIdx.x * F_BN;

    const uint32_t sAs = smem_u32(As);
    const uint32_t sBs = smem_u32(Bs);
    const __half* xh = g_xh;

    // Hoisted ldmatrix per-thread offsets (in halves, excluding stage base):
    //  A (x4: m0 rows k0-7, m1 rows k8-15 ...): row = wm+mf*16+(lane&15), k += (lane>>4)*8
    const uint32_t aOff = (uint32_t)((wm + (lane & 15)) * F_ST + ((lane >> 4) << 3));
    //  B (x4: mats = [n grp0,k0-7],[n grp0,k8-15],[n grp1,k0-7],[n grp1,k8-15]):
    //  lanes 0-7 -> m0, 8-15 -> m1, 16-23 -> m2, 24-31 -> m3
    const uint32_t bOff = (uint32_t)((wn + (lane & 7) + (((lane >> 4) & 1) << 3)) * F_ST
                                     + (((lane >> 3) & 1) << 3));

    // preload mix tile (128x8 f32 = 256 float4) and bg tiles (8x128 f32 = 256 float4)
    if (tid < 256) {
        ((float4*)mixs)[tid] = ((const float4*)(g_mix + (size_t)m0 * E_DIM))[tid];
    } else {
        const int t2 = tid - 256;
        const int e = t2 >> 5, c = (t2 & 31) * 4;
        *(float4*)(bgs + e * F_BN + c) = *(const float4*)(bg + (size_t)e * D_DIM + n0 + c);
    }

    // one flat stage's loads: A 1 chunk + B 1 chunk per thread (512 chunks each)
#define H_LOAD_STAGE(flat) do {                                                      \
    const int _buf = (flat) & (N_STAGES - 1);                                        \
    const int _e = (flat) >> 5;                                                      \
    const int _k0 = ((flat) & 31) * F_BK;                                            \
    const __half* _Bsrc = g_wh + (size_t)_e * D_DIM * D_DIM + (size_t)n0 * D_DIM;    \
    const int _r = tid >> 2, _q = tid & 3;                                           \
    CP_ASYNC16(sAs + (uint32_t)((_buf * F_STAGE + _r * F_ST + _q * 8) * 2),          \
               xh + (size_t)(m0 + _r) * D_DIM + _k0 + _q * 8);                       \
    CP_ASYNC16(sBs + (uint32_t)((_buf * F_STAGE + _r * F_ST + _q * 8) * 2),          \
               _Bsrc + (size_t)_r * D_DIM + _k0 + _q * 8);                           \
} while (0)

    // prologue: stages 0..2
#pragma unroll
    for (int s = 0; s < N_STAGES - 1; ++s) {
        H_LOAD_STAGE(s);
        asm volatile("cp.async.commit_group;" ::: "memory");
    }

    float accOut[2][4][4];
#pragma unroll
    for (int a = 0; a < 2; ++a)
#pragma unroll
        for (int b = 0; b < 4; ++b)
#pragma unroll
            for (int c = 0; c < 4; ++c) accOut[a][b][c] = 0.0f;

    float acc[2][4][4];
#pragma unroll
    for (int a = 0; a < 2; ++a)
#pragma unroll
        for (int b = 0; b < 4; ++b)
#pragma unroll
            for (int c = 0; c < 4; ++c) acc[a][b][c] = 0.0f;

    for (int flat = 0; flat < N_FLAT; ++flat) {
        asm volatile("cp.async.wait_group 2;" ::: "memory");
        __syncthreads();

        if (flat + N_STAGES - 1 < N_FLAT)
            H_LOAD_STAGE(flat + N_STAGES - 1);
        asm volatile("cp.async.commit_group;" ::: "memory");

        const uint32_t aBase = sAs + 2u * ((uint32_t)(flat & (N_STAGES - 1)) * F_STAGE + aOff);
        const uint32_t bBase = sBs + 2u * ((uint32_t)(flat & (N_STAGES - 1)) * F_STAGE + bOff);
#pragma unroll
        for (int kk = 0; kk < F_BK; kk += 16) {
            uint32_t afr[2][4], bfr[4][2];
#pragma unroll
            for (int mf = 0; mf < 2; ++mf)
                ldmatrix_x4(afr[mf], aBase + 2u * (uint32_t)(mf * 16 * F_ST + kk));
#pragma unroll
            for (int pair = 0; pair < 2; ++pair) {
                uint32_t r[4];
                ldmatrix_x4(r, bBase + 2u * (uint32_t)(pair * 16 * F_ST + kk));
                bfr[2 * pair][0] = r[0]; bfr[2 * pair][1] = r[1];
                bfr[2 * pair + 1][0] = r[2]; bfr[2 * pair + 1][1] = r[3];
            }
#pragma unroll
            for (int mf = 0; mf < 2; ++mf)
#pragma unroll
                for (int nf = 0; nf < 4; ++nf)
                    mma16n8k16h(acc[mf][nf], afr[mf], bfr[nf]);
        }

        // expert boundary: fold into accOut, reset acc
        if ((flat & 31) == 31) {
            const int e = flat >> 5;
#pragma unroll
            for (int mf = 0; mf < 2; ++mf) {
                const int r = wm + mf * 16 + g;
                const float mx0 = mixs[r * E_DIM + e];
                const float mx1 = mixs[(r + 8) * E_DIM + e];
#pragma unroll
                for (int nf = 0; nf < 4; ++nf) {
                    const int c = wn + nf * 8 + 2 * tg;
                    const float b0 = bgs[e * F_BN + c];
                    const float b1 = bgs[e * F_BN + c + 1];
                    accOut[mf][nf][0] += mx0 / (1.0f + __expf(-(acc[mf][nf][0] + b0)));
                    accOut[mf][nf][1] += mx0 / (1.0f + __expf(-(acc[mf][nf][1] + b1)));
                    accOut[mf][nf][2] += mx1 / (1.0f + __expf(-(acc[mf][nf][2] + b0)));
                    accOut[mf][nf][3] += mx1 / (1.0f + __expf(-(acc[mf][nf][3] + b1)));
                    acc[mf][nf][0] = 0.0f; acc[mf][nf][1] = 0.0f;
                    acc[mf][nf][2] = 0.0f; acc[mf][nf][3] = 0.0f;
                }
            }
        }
    }

    // write 128x128 tile (each warp: 32 rows x 32 cols)
#pragma unroll
    for (int mf = 0; mf < 2; ++mf) {
        const int r0 = m0 + wm + mf * 16 + g;
#pragma unroll
        for (int nf = 0; nf < 4; ++nf) {
            const int c = n0 + wn + nf * 8 + 2 * tg;
            *(float2*)(out + (size_t)r0 * D_DIM + c) =
                make_float2(accOut[mf][nf][0], accOut[mf][nf][1]);
            *(float2*)(out + (size_t)(r0 + 8) * D_DIM + c) =
                make_float2(accOut[mf][nf][2], accOut[mf][nf][3]);
        }
    }
}

// ===========================================================================
// Inputs: x, Wg, bg, Wf, bf, Wt, bt, alpha, num
// ===========================================================================
extern "C" void kernel_launch(void* const* d_in, const int* in_sizes, int n_in,
                              void* d_out, int out_size)
{
    const float* x     = (const float*)d_in[0];
    const float* Wg    = (const float*)d_in[1];
    const float* bg    = (const float*)d_in[2];
    const float* Wf    = (const float*)d_in[3];
    const float* bf    = (const float*)d_in[4];
    const float* Wt    = (const float*)d_in[5];
    const float* bt    = (const float*)d_in[6];
    const float* alpha = (const float*)d_in[7];
    float* out = (float*)d_out;

    const int BT = in_sizes[0] / D_DIM;    // 16384
    const int n_x = BT * D_DIM;            // 16777216
    const int n_w = E_DIM * D_DIM * D_DIM; // 8388608

    __half* xh_ptr = nullptr;
    __half* wh_ptr = nullptr;
    cudaGetSymbolAddress((void**)&xh_ptr, g_xh);
    cudaGetSymbolAddress((void**)&wh_ptr, g_wh);

    cudaFuncSetAttribute(moe_gate_h,
                         cudaFuncAttributeMaxDynamicSharedMemorySize, SMEM_BYTES);

    f2h_kernel<<<n_x / 1024, 256>>>(x, xh_ptr, n_x);
    f2h_kernel<<<n_w / 1024, 256>>>(Wg, wh_ptr, n_w);

    routing_kernel<<<(BT + 3) / 4, 128>>>(x, Wf, bf, Wt, bt, alpha, BT);

    dim3 grid(D_DIM / F_BN, BT / F_BM);   // (8, 128) = 1024 CTAs
    moe_gate_h<<<grid, N_THREADS, SMEM_BYTES>>>(bg, out);
}

// round 10
// speedup vs baseline: 1.4267x; 1.0688x over previous
#include <cuda_runtime.h>
#include <cuda_fp16.h>
#include <cstdint>
#include <math.h>

// Problem constants: B=8, T=2048, D=1024, E=8 -> BT=16384
#define D_DIM 1024
#define E_DIM 8
#define BT_MAX 16384

__device__ float g_mix[BT_MAX * E_DIM];
__device__ __half g_xh[BT_MAX * D_DIM];            // 32 MB fp16 copy of x
__device__ __half g_wh[E_DIM * D_DIM * D_DIM];     // 16 MB fp16 copy of Wg

// ===========================================================================
// PTX helpers
// ===========================================================================
__device__ __forceinline__ uint32_t smem_u32(const void* p) {
    uint32_t a;
    asm("{ .reg .u64 t; cvta.to.shared.u64 t, %1; cvt.u32.u64 %0, t; }" : "=r"(a) : "l"(p));
    return a;
}

#define CP_ASYNC16(dst, src) \
    asm volatile("cp.async.cg.shared.global [%0], [%1], 16;" :: "r"(dst), "l"(src) : "memory")

__device__ __forceinline__ void ldmatrix_x4(uint32_t* r, uint32_t addr) {
    asm volatile("ldmatrix.sync.aligned.m8n8.x4.shared.b16 {%0,%1,%2,%3}, [%4];"
        : "=r"(r[0]), "=r"(r[1]), "=r"(r[2]), "=r"(r[3]) : "r"(addr));
}

__device__ __forceinline__ void mma16n8k16h(float* d, const uint32_t* a, const uint32_t* b) {
    asm volatile("mma.sync.aligned.m16n8k16.row.col.f32.f16.f16.f32 "
        "{%0,%1,%2,%3}, {%4,%5,%6,%7}, {%8,%9}, {%0,%1,%2,%3};"
        : "+f"(d[0]), "+f"(d[1]), "+f"(d[2]), "+f"(d[3])
        : "r"(a[0]), "r"(a[1]), "r"(a[2]), "r"(a[3]), "r"(b[0]), "r"(b[1]));
}

// ===========================================================================
// Kernel 0: fp32 -> fp16 conversion
// ===========================================================================
__global__ __launch_bounds__(256) void f2h_kernel(const float* __restrict__ src,
                                                  __half* __restrict__ dst, int n)
{
    int i = (blockIdx.x * 256 + threadIdx.x) * 4;
    if (i < n) {
        float4 v = *(const float4*)(src + i);
        __half2 h0 = __floats2half2_rn(v.x, v.y);
        __half2 h1 = __floats2half2_rn(v.z, v.w);
        uint2 u;
        u.x = *(uint32_t*)&h0;
        u.y = *(uint32_t*)&h1;
        *(uint2*)(dst + i) = u;
    }
}

// ===========================================================================
// Kernel 1: routing (verified; fp32)
// ===========================================================================
__global__ __launch_bounds__(128) void routing_kernel(
    const float* __restrict__ x,
    const float* __restrict__ Wf, const float* __restrict__ bf,
    const float* __restrict__ Wt, const float* __restrict__ bt,
    const float* __restrict__ alpha, int BT)
{
    int warp = blockIdx.x * (blockDim.x >> 5) + (threadIdx.x >> 5);
    int lane = threadIdx.x & 31;
    if (warp >= BT) return;

    const float* xr = x + (size_t)warp * D_DIM;
    float xv[32];
#pragma unroll
    for (int j = 0; j < 32; ++j) xv[j] = xr[lane + 32 * j];

    float dots[16];
#pragma unroll
    for (int r = 0; r < 16; ++r) {
        const float* w = (r < 8) ? (Wt + r * D_DIM) : (Wf + (r - 8) * D_DIM);
        float s = 0.0f;
#pragma unroll
        for (int j = 0; j < 32; ++j) s += xv[j] * w[lane + 32 * j];
#pragma unroll
        for (int off = 16; off > 0; off >>= 1)
            s += __shfl_xor_sync(0xffffffffu, s, off);
        dots[r] = s;
    }

    float tl[8], fl[8];
#pragma unroll
    for (int e = 0; e < 8; ++e) { tl[e] = dots[e] + bt[e]; fl[e] = dots[8 + e] + bf[e]; }

    float v0 = tl[0]; int i0 = 0;
    float v1 = -INFINITY; int i1 = -1;
#pragma unroll
    for (int e = 1; e < 8; ++e) {
        if (tl[e] > v0) { v1 = v0; i1 = i0; v0 = tl[e]; i0 = e; }
        else if (tl[e] > v1) { v1 = tl[e]; i1 = e; }
    }
    float p1 = expf(v1 - v0);
    float sv0 = 1.0f / (1.0f + p1);
    float sv1 = p1 * sv0;

    float mf = fl[0];
#pragma unroll
    for (int e = 1; e < 8; ++e) mf = fmaxf(mf, fl[e]);
    float ef[8]; float se = 0.0f;
#pragma unroll
    for (int e = 0; e < 8; ++e) { ef[e] = expf(fl[e] - mf); se += ef[e]; }
    float inv_se = 1.0f / se;

    float a = 1.0f / (1.0f + expf(-alpha[0]));
    float one_m_a = 1.0f - a;

#pragma unroll
    for (int e = 0; e < 8; ++e) {
        float tp = (e == i0) ? sv0 : ((e == i1) ? sv1 : 0.0f);
        float m = a * tp + one_m_a * ef[e] * inv_se;
        if (lane == e) g_mix[(size_t)warp * E_DIM + e] = m;
    }
}

// ===========================================================================
// Kernel 2: fp16 mma.sync fused MoE gate, 512 threads (16 warps).
//   CTA tile 128x128, warp grid 4m x 4n, warp tile 32x32, m16n8k16,
//   BK=64 (128 flat stages), 3-stage cp.async, ldmatrix.x4 fragments,
//   flattened expert loop with register fold.
// ===========================================================================
#define F_BM 128
#define F_BN 128
#define F_BK 64
#define F_ST 72                    // halves per smem row (64 + 8 pad) = 144 B
#define F_STAGE (F_BM * F_ST)      // 9216 halves per stage
#define N_STAGES 3
#define KCH (D_DIM / F_BK)                // 16 k-chunks per expert
#define N_FLAT (E_DIM * KCH)              // 128
#define N_THREADS 512

// dynamic smem layout (bytes)
#define SMB_A    0                                  // 3 * 18432 = 55296
#define SMB_B    (SMB_A + N_STAGES * F_STAGE * 2)   // 55296..110592
#define SMB_MIX  (SMB_B + N_STAGES * F_STAGE * 2)   // 110592, 4096 B
#define SMB_BGS  (SMB_MIX + F_BM * E_DIM * 4)       // 114688, 4096 B
#define SMEM_BYTES (SMB_BGS + E_DIM * F_BN * 4)     // 118784

__global__ __launch_bounds__(N_THREADS, 1) void moe_gate_h(
    const float* __restrict__ bg,
    float* __restrict__ out)
{
    extern __shared__ char smc[];
    __half* As = (__half*)(smc + SMB_A);
    __half* Bs = (__half*)(smc + SMB_B);
    float* mixs = (float*)(smc + SMB_MIX);
    float* bgs  = (float*)(smc + SMB_BGS);

    const int tid = threadIdx.x;
    const int warp = tid >> 5, lane = tid & 31;
    const int wm = (warp & 3) * 32;       // 4 m-warps
    const int wn = (warp >> 2) * 32;      // 4 n-warps
    const int g = lane >> 2, tg = lane & 3;
    const int m0 = blockIdx.y * F_BM, n0 = blockIdx.x * F_BN;

    const uint32_t sAs = smem_u32(As);
    const uint32_t sBs = smem_u32(Bs);

    // Hoisted ldmatrix per-thread offsets (halves, excluding stage/kk):
    const uint32_t aOff = (uint32_t)((wm + (lane & 15)) * F_ST + ((lane >> 4) << 3));
    const uint32_t bOff = (uint32_t)((wn + (lane & 7) + (((lane >> 4) & 1) << 3)) * F_ST
                                     + (((lane >> 3) & 1) << 3));

    // Hoisted load-offsets: thread handles rows r and r+64, chunk q (same q both)
    const int ldR = tid >> 3, ldQ = tid & 7;                 // r in [0,64), q in [0,8)
    const uint32_t ldSm = (uint32_t)((ldR * F_ST + ldQ * 8) * 2);   // smem byte offset
    const __half* ldA = g_xh + (size_t)(m0 + ldR) * D_DIM + ldQ * 8;
    const __half* ldBbase = g_wh + (size_t)(n0 + ldR) * D_DIM + ldQ * 8;

    // preload mix tile (128x8 f32 = 256 float4) and bg tiles (8x128 f32 = 256 float4)
    if (tid < 256) {
        ((float4*)mixs)[tid] = ((const float4*)(g_mix + (size_t)m0 * E_DIM))[tid];
    } else {
        const int t2 = tid - 256;
        const int e = t2 >> 5, c = (t2 & 31) * 4;
        *(float4*)(bgs + e * F_BN + c) = *(const float4*)(bg + (size_t)e * D_DIM + n0 + c);
    }

    // one flat stage's loads: A 2 chunks + B 2 chunks per thread
#define H_LOAD_STAGE(flat) do {                                                      \
    const uint32_t _sm = (uint32_t)((flat) % N_STAGES) * (F_STAGE * 2u) + ldSm;      \
    const int _k0 = ((flat) & (KCH - 1)) << 6;                                       \
    const __half* _a = ldA + _k0;                                                    \
    const __half* _b = ldBbase + ((size_t)((flat) >> 4) * (D_DIM * D_DIM)) + _k0;    \
    CP_ASYNC16(sAs + _sm, _a);                                                       \
    CP_ASYNC16(sAs + _sm + 64u * F_ST * 2u, _a + 64 * D_DIM);                        \
    CP_ASYNC16(sBs + _sm, _b);                                                       \
    CP_ASYNC16(sBs + _sm + 64u * F_ST * 2u, _b + 64 * D_DIM);                        \
} while (0)

    // prologue: stages 0..1
#pragma unroll
    for (int s = 0; s < N_STAGES - 1; ++s) {
        H_LOAD_STAGE(s);
        asm volatile("cp.async.commit_group;" ::: "memory");
    }

    float accOut[2][4][4];
#pragma unroll
    for (int a = 0; a < 2; ++a)
#pragma unroll
        for (int b = 0; b < 4; ++b)
#pragma unroll
            for (int c = 0; c < 4; ++c) accOut[a][b][c] = 0.0f;

    float acc[2][4][4];
#pragma unroll
    for (int a = 0; a < 2; ++a)
#pragma unroll
        for (int b = 0; b < 4; ++b)
#pragma unroll
            for (int c = 0; c < 4; ++c) acc[a][b][c] = 0.0f;

    for (int flat = 0; flat < N_FLAT; ++flat) {
        asm volatile("cp.async.wait_group 1;" ::: "memory");
        __syncthreads();

        if (flat + N_STAGES - 1 < N_FLAT)
            H_LOAD_STAGE(flat + N_STAGES - 1);
        asm volatile("cp.async.commit_group;" ::: "memory");

        const uint32_t stB = (uint32_t)(flat % N_STAGES) * (F_STAGE * 2u);
        const uint32_t aBase = sAs + stB + 2u * aOff;
        const uint32_t bBase = sBs + stB + 2u * bOff;
#pragma unroll
        for (int kk = 0; kk < F_BK; kk += 16) {
            uint32_t afr[2][4], bfr[4][2];
#pragma unroll
            for (int mf = 0; mf < 2; ++mf)
                ldmatrix_x4(afr[mf], aBase + 2u * (uint32_t)(mf * 16 * F_ST + kk));
#pragma unroll
            for (int pair = 0; pair < 2; ++pair) {
                uint32_t r[4];
                ldmatrix_x4(r, bBase + 2u * (uint32_t)(pair * 16 * F_ST + kk));
                bfr[2 * pair][0] = r[0]; bfr[2 * pair][1] = r[1];
                bfr[2 * pair + 1][0] = r[2]; bfr[2 * pair + 1][1] = r[3];
            }
#pragma unroll
            for (int mf = 0; mf < 2; ++mf)
#pragma unroll
                for (int nf = 0; nf < 4; ++nf)
                    mma16n8k16h(acc[mf][nf], afr[mf], bfr[nf]);
        }

        // expert boundary: fold into accOut, reset acc
        if ((flat & (KCH - 1)) == KCH - 1) {
            const int e = flat >> 4;
#pragma unroll
            for (int mf = 0; mf < 2; ++mf) {
                const int r = wm + mf * 16 + g;
                const float mx0 = mixs[r * E_DIM + e];
                const float mx1 = mixs[(r + 8) * E_DIM + e];
#pragma unroll
                for (int nf = 0; nf < 4; ++nf) {
                    const int c = wn + nf * 8 + 2 * tg;
                    const float b0 = bgs[e * F_BN + c];
                    const float b1 = bgs[e * F_BN + c + 1];
                    accOut[mf][nf][0] += mx0 / (1.0f + __expf(-(acc[mf][nf][0] + b0)));
                    accOut[mf][nf][1] += mx0 / (1.0f + __expf(-(acc[mf][nf][1] + b1)));
                    accOut[mf][nf][2] += mx1 / (1.0f + __expf(-(acc[mf][nf][2] + b0)));
                    accOut[mf][nf][3] += mx1 / (1.0f + __expf(-(acc[mf][nf][3] + b1)));
                    acc[mf][nf][0] = 0.0f; acc[mf][nf][1] = 0.0f;
                    acc[mf][nf][2] = 0.0f; acc[mf][nf][3] = 0.0f;
                }
            }
        }
    }

    // write 128x128 tile (each warp: 32 rows x 32 cols)
#pragma unroll
    for (int mf = 0; mf < 2; ++mf) {
        const int r0 = m0 + wm + mf * 16 + g;
#pragma unroll
        for (int nf = 0; nf < 4; ++nf) {
            const int c = n0 + wn + nf * 8 + 2 * tg;
            *(float2*)(out + (size_t)r0 * D_DIM + c) =
                make_float2(accOut[mf][nf][0], accOut[mf][nf][1]);
            *(float2*)(out + (size_t)(r0 + 8) * D_DIM + c) =
                make_float2(accOut[mf][nf][2], accOut[mf][nf][3]);
        }
    }
}

// ===========================================================================
// Inputs: x, Wg, bg, Wf, bf, Wt, bt, alpha, num
// ===========================================================================
extern "C" void kernel_launch(void* const* d_in, const int* in_sizes, int n_in,
                              void* d_out, int out_size)
{
    const float* x     = (const float*)d_in[0];
    const float* Wg    = (const float*)d_in[1];
    const float* bg    = (const float*)d_in[2];
    const float* Wf    = (const float*)d_in[3];
    const float* bf    = (const float*)d_in[4];
    const float* Wt    = (const float*)d_in[5];
    const float* bt    = (const float*)d_in[6];
    const float* alpha = (const float*)d_in[7];
    float* out = (float*)d_out;

    const int BT = in_sizes[0] / D_DIM;    // 16384
    const int n_x = BT * D_DIM;            // 16777216
    const int n_w = E_DIM * D_DIM * D_DIM; // 8388608

    __half* xh_ptr = nullptr;
    __half* wh_ptr = nullptr;
    cudaGetSymbolAddress((void**)&xh_ptr, g_xh);
    cudaGetSymbolAddress((void**)&wh_ptr, g_wh);

    cudaFuncSetAttribute(moe_gate_h,
                         cudaFuncAttributeMaxDynamicSharedMemorySize, SMEM_BYTES);

    f2h_kernel<<<n_x / 1024, 256>>>(x, xh_ptr, n_x);
    f2h_kernel<<<n_w / 1024, 256>>>(Wg, wh_ptr, n_w);

    routing_kernel<<<(BT + 3) / 4, 128>>>(x, Wf, bf, Wt, bt, alpha, BT);

    dim3 grid(D_DIM / F_BN, BT / F_BM);   // (8, 128) = 1024 CTAs
    moe_gate_h<<<grid, N_THREADS, SMEM_BYTES>>>(bg, out);
}

// round 11
// speedup vs baseline: 1.4728x; 1.0323x over previous
#include <cuda_runtime.h>
#include <cuda_fp16.h>
#include <cstdint>
#include <math.h>

// Problem constants: B=8, T=2048, D=1024, E=8 -> BT=16384
#define D_DIM 1024
#define E_DIM 8
#define BT_MAX 16384

__device__ float g_mix[BT_MAX * E_DIM];
__device__ __half g_xh[BT_MAX * D_DIM];            // 32 MB fp16 copy of x
__device__ __half g_wh[E_DIM * D_DIM * D_DIM];     // 16 MB fp16 copy of Wg

// ===========================================================================
// PTX helpers
// ===========================================================================
__device__ __forceinline__ uint32_t smem_u32(const void* p) {
    uint32_t a;
    asm("{ .reg .u64 t; cvta.to.shared.u64 t, %1; cvt.u32.u64 %0, t; }" : "=r"(a) : "l"(p));
    return a;
}

#define CP_ASYNC16(dst, src) \
    asm volatile("cp.async.cg.shared.global [%0], [%1], 16;" :: "r"(dst), "l"(src) : "memory")

__device__ __forceinline__ void ldmatrix_x4(uint32_t* r, uint32_t addr) {
    asm volatile("ldmatrix.sync.aligned.m8n8.x4.shared.b16 {%0,%1,%2,%3}, [%4];"
        : "=r"(r[0]), "=r"(r[1]), "=r"(r[2]), "=r"(r[3]) : "r"(addr));
}

__device__ __forceinline__ void mma16n8k16h(float* d, const uint32_t* a, const uint32_t* b) {
    asm volatile("mma.sync.aligned.m16n8k16.row.col.f32.f16.f16.f32 "
        "{%0,%1,%2,%3}, {%4,%5,%6,%7}, {%8,%9}, {%0,%1,%2,%3};"
        : "+f"(d[0]), "+f"(d[1]), "+f"(d[2]), "+f"(d[3])
        : "r"(a[0]), "r"(a[1]), "r"(a[2]), "r"(a[3]), "r"(b[0]), "r"(b[1]));
}

// ===========================================================================
// Kernel 0: fp32 -> fp16 conversion
// ===========================================================================
__global__ __launch_bounds__(256) void f2h_kernel(const float* __restrict__ src,
                                                  __half* __restrict__ dst, int n)
{
    int i = (blockIdx.x * 256 + threadIdx.x) * 4;
    if (i < n) {
        float4 v = *(const float4*)(src + i);
        __half2 h0 = __floats2half2_rn(v.x, v.y);
        __half2 h1 = __floats2half2_rn(v.z, v.w);
        uint2 u;
        u.x = *(uint32_t*)&h0;
        u.y = *(uint32_t*)&h1;
        *(uint2*)(dst + i) = u;
    }
}

// ===========================================================================
// Kernel 1: routing (verified; fp32)
// ===========================================================================
__global__ __launch_bounds__(128) void routing_kernel(
    const float* __restrict__ x,
    const float* __restrict__ Wf, const float* __restrict__ bf,
    const float* __restrict__ Wt, const float* __restrict__ bt,
    const float* __restrict__ alpha, int BT)
{
    int warp = blockIdx.x * (blockDim.x >> 5) + (threadIdx.x >> 5);
    int lane = threadIdx.x & 31;
    if (warp >= BT) return;

    const float* xr = x + (size_t)warp * D_DIM;
    float xv[32];
#pragma unroll
    for (int j = 0; j < 32; ++j) xv[j] = xr[lane + 32 * j];

    float dots[16];
#pragma unroll
    for (int r = 0; r < 16; ++r) {
        const float* w = (r < 8) ? (Wt + r * D_DIM) : (Wf + (r - 8) * D_DIM);
        float s = 0.0f;
#pragma unroll
        for (int j = 0; j < 32; ++j) s += xv[j] * w[lane + 32 * j];
#pragma unroll
        for (int off = 16; off > 0; off >>= 1)
            s += __shfl_xor_sync(0xffffffffu, s, off);
        dots[r] = s;
    }

    float tl[8], fl[8];
#pragma unroll
    for (int e = 0; e < 8; ++e) { tl[e] = dots[e] + bt[e]; fl[e] = dots[8 + e] + bf[e]; }

    float v0 = tl[0]; int i0 = 0;
    float v1 = -INFINITY; int i1 = -1;
#pragma unroll
    for (int e = 1; e < 8; ++e) {
        if (tl[e] > v0) { v1 = v0; i1 = i0; v0 = tl[e]; i0 = e; }
        else if (tl[e] > v1) { v1 = tl[e]; i1 = e; }
    }
    float p1 = expf(v1 - v0);
    float sv0 = 1.0f / (1.0f + p1);
    float sv1 = p1 * sv0;

    float mf = fl[0];
#pragma unroll
    for (int e = 1; e < 8; ++e) mf = fmaxf(mf, fl[e]);
    float ef[8]; float se = 0.0f;
#pragma unroll
    for (int e = 0; e < 8; ++e) { ef[e] = expf(fl[e] - mf); se += ef[e]; }
    float inv_se = 1.0f / se;

    float a = 1.0f / (1.0f + expf(-alpha[0]));
    float one_m_a = 1.0f - a;

#pragma unroll
    for (int e = 0; e < 8; ++e) {
        float tp = (e == i0) ? sv0 : ((e == i1) ? sv1 : 0.0f);
        float m = a * tp + one_m_a * ef[e] * inv_se;
        if (lane == e) g_mix[(size_t)warp * E_DIM + e] = m;
    }
}

// ===========================================================================
// Kernel 2: fp16 mma.sync fused MoE gate, 256 threads, 2 CTAs/SM.
//   CTA tile 128(m) x 64(n); warp grid 4m x 2n; warp tile 32x32; m16n8k16;
//   BK=64, 3-stage cp.async; ldmatrix.x4 fragments; flattened expert loop.
// ===========================================================================
#define F_BM 128
#define F_BN 64
#define F_BK 64
#define F_ST 72                    // halves per smem row (64 + 8 pad) = 144 B
#define A_STAGE (F_BM * F_ST)      // 9216 halves
#define B_STAGE (F_BN * F_ST)      // 4608 halves
#define N_STAGES 3
#define KCH (D_DIM / F_BK)                // 16 k-chunks per expert
#define N_FLAT (E_DIM * KCH)              // 128
#define N_THREADS 256

// dynamic smem layout (bytes)
#define SMB_A    0                                  // 3 * 18432 = 55296
#define SMB_B    (SMB_A + N_STAGES * A_STAGE * 2)   // 55296..82944
#define SMB_MIX  (SMB_B + N_STAGES * B_STAGE * 2)   // 82944, 4096 B
#define SMB_BGS  (SMB_MIX + F_BM * E_DIM * 4)       // 87040, 2048 B
#define SMEM_BYTES (SMB_BGS + E_DIM * F_BN * 4)     // 89088

__global__ __launch_bounds__(N_THREADS, 2) void moe_gate_h(
    const float* __restrict__ bg,
    float* __restrict__ out)
{
    extern __shared__ char smc[];
    __half* As = (__half*)(smc + SMB_A);
    __half* Bs = (__half*)(smc + SMB_B);
    float* mixs = (float*)(smc + SMB_MIX);
    float* bgs  = (float*)(smc + SMB_BGS);

    const int tid = threadIdx.x;
    const int warp = tid >> 5, lane = tid & 31;
    const int wm = (warp & 3) * 32;       // 4 m-warps
    const int wn = (warp >> 2) * 32;      // 2 n-warps
    const int g = lane >> 2, tg = lane & 3;
    const int m0 = blockIdx.y * F_BM, n0 = blockIdx.x * F_BN;

    const uint32_t sAs = smem_u32(As);
    const uint32_t sBs = smem_u32(Bs);

    // Hoisted ldmatrix per-thread offsets (halves, excluding stage/kk):
    const uint32_t aOff = (uint32_t)((wm + (lane & 15)) * F_ST + ((lane >> 4) << 3));
    const uint32_t bOff = (uint32_t)((wn + (lane & 7) + (((lane >> 4) & 1) << 3)) * F_ST
                                     + (((lane >> 3) & 1) << 3));

    // Hoisted load-offsets: thread covers A rows r+{0,32,64,96}, B rows r+{0,32}
    const int ldR = tid >> 3, ldQ = tid & 7;                 // r in [0,32), q in [0,8)
    const uint32_t ldSm = (uint32_t)((ldR * F_ST + ldQ * 8) * 2);   // smem byte offset
    const __half* ldA = g_xh + (size_t)(m0 + ldR) * D_DIM + ldQ * 8;
    const __half* ldBbase = g_wh + (size_t)(n0 + ldR) * D_DIM + ldQ * 8;

    // preload mix tile (128x8 f32 = 256 float4) and bg tiles (8x64 f32 = 128 float4)
    ((float4*)mixs)[tid] = ((const float4*)(g_mix + (size_t)m0 * E_DIM))[tid];
    if (tid < 128) {
        const int e = tid >> 4, c = (tid & 15) * 4;
        *(float4*)(bgs + e * F_BN + c) = *(const float4*)(bg + (size_t)e * D_DIM + n0 + c);
    }

    // one flat stage's loads: A 4 chunks + B 2 chunks per thread
#define H_LOAD_STAGE(flat) do {                                                      \
    const uint32_t _st = (uint32_t)((flat) % N_STAGES);                              \
    const uint32_t _smA = _st * (A_STAGE * 2u) + ldSm;                               \
    const uint32_t _smB = _st * (B_STAGE * 2u) + ldSm;                               \
    const int _k0 = ((flat) & (KCH - 1)) << 6;                                       \
    const __half* _a = ldA + _k0;                                                    \
    const __half* _b = ldBbase + ((size_t)((flat) >> 4) * (D_DIM * D_DIM)) + _k0;    \
    CP_ASYNC16(sAs + _smA, _a);                                                      \
    CP_ASYNC16(sAs + _smA + 32u * F_ST * 2u, _a + 32 * D_DIM);                       \
    CP_ASYNC16(sAs + _smA + 64u * F_ST * 2u, _a + 64 * D_DIM);                       \
    CP_ASYNC16(sAs + _smA + 96u * F_ST * 2u, _a + 96 * D_DIM);                       \
    CP_ASYNC16(sBs + _smB, _b);                                                      \
    CP_ASYNC16(sBs + _smB + 32u * F_ST * 2u, _b + 32 * D_DIM);                       \
} while (0)

    // prologue: stages 0..1
#pragma unroll
    for (int s = 0; s < N_STAGES - 1; ++s) {
        H_LOAD_STAGE(s);
        asm volatile("cp.async.commit_group;" ::: "memory");
    }

    float accOut[2][4][4];
#pragma unroll
    for (int a = 0; a < 2; ++a)
#pragma unroll
        for (int b = 0; b < 4; ++b)
#pragma unroll
            for (int c = 0; c < 4; ++c) accOut[a][b][c] = 0.0f;

    float acc[2][4][4];
#pragma unroll
    for (int a = 0; a < 2; ++a)
#pragma unroll
        for (int b = 0; b < 4; ++b)
#pragma unroll
            for (int c = 0; c < 4; ++c) acc[a][b][c] = 0.0f;

    for (int flat = 0; flat < N_FLAT; ++flat) {
        asm volatile("cp.async.wait_group 1;" ::: "memory");
        __syncthreads();

        if (flat + N_STAGES - 1 < N_FLAT)
            H_LOAD_STAGE(flat + N_STAGES - 1);
        asm volatile("cp.async.commit_group;" ::: "memory");

        const uint32_t st = (uint32_t)(flat % N_STAGES);
        const uint32_t aBase = sAs + st * (A_STAGE * 2u) + 2u * aOff;
        const uint32_t bBase = sBs + st * (B_STAGE * 2u) + 2u * bOff;
#pragma unroll
        for (int kk = 0; kk < F_BK; kk += 16) {
            uint32_t afr[2][4], bfr[4][2];
#pragma unroll
            for (int mf = 0; mf < 2; ++mf)
                ldmatrix_x4(afr[mf], aBase + 2u * (uint32_t)(mf * 16 * F_ST + kk));
#pragma unroll
            for (int pair = 0; pair < 2; ++pair) {
                uint32_t r[4];
                ldmatrix_x4(r, bBase + 2u * (uint32_t)(pair * 16 * F_ST + kk));
                bfr[2 * pair][0] = r[0]; bfr[2 * pair][1] = r[1];
                bfr[2 * pair + 1][0] = r[2]; bfr[2 * pair + 1][1] = r[3];
            }
#pragma unroll
            for (int mf = 0; mf < 2; ++mf)
#pragma unroll
                for (int nf = 0; nf < 4; ++nf)
                    mma16n8k16h(acc[mf][nf], afr[mf], bfr[nf]);
        }

        // expert boundary: fold into accOut, reset acc
        if ((flat & (KCH - 1)) == KCH - 1) {
            const int e = flat >> 4;
#pragma unroll
            for (int mf = 0; mf < 2; ++mf) {
                const int r = wm + mf * 16 + g;
                const float mx0 = mixs[r * E_DIM + e];
                const float mx1 = mixs[(r + 8) * E_DIM + e];
#pragma unroll
                for (int nf = 0; nf < 4; ++nf) {
                    const int c = wn + nf * 8 + 2 * tg;
                    const float b0 = bgs[e * F_BN + c];
                    const float b1 = bgs[e * F_BN + c + 1];
                    accOut[mf][nf][0] += mx0 / (1.0f + __expf(-(acc[mf][nf][0] + b0)));
                    accOut[mf][nf][1] += mx0 / (1.0f + __expf(-(acc[mf][nf][1] + b1)));
                    accOut[mf][nf][2] += mx1 / (1.0f + __expf(-(acc[mf][nf][2] + b0)));
                    accOut[mf][nf][3] += mx1 / (1.0f + __expf(-(acc[mf][nf][3] + b1)));
                    acc[mf][nf][0] = 0.0f; acc[mf][nf][1] = 0.0f;
                    acc[mf][nf][2] = 0.0f; acc[mf][nf][3] = 0.0f;
                }
            }
        }
    }

    // write 128x64 tile (each warp: 32 rows x 32 cols)
#pragma unroll
    for (int mf = 0; mf < 2; ++mf) {
        const int r0 = m0 + wm + mf * 16 + g;
#pragma unroll
        for (int nf = 0; nf < 4; ++nf) {
            const int c = n0 + wn + nf * 8 + 2 * tg;
            *(float2*)(out + (size_t)r0 * D_DIM + c) =
                make_float2(accOut[mf][nf][0], accOut[mf][nf][1]);
            *(float2*)(out + (size_t)(r0 + 8) * D_DIM + c) =
                make_float2(accOut[mf][nf][2], accOut[mf][nf][3]);
        }
    }
}

// ===========================================================================
// Inputs: x, Wg, bg, Wf, bf, Wt, bt, alpha, num
// ===========================================================================
extern "C" void kernel_launch(void* const* d_in, const int* in_sizes, int n_in,
                              void* d_out, int out_size)
{
    const float* x     = (const float*)d_in[0];
    const float* Wg    = (const float*)d_in[1];
    const float* bg    = (const float*)d_in[2];
    const float* Wf    = (const float*)d_in[3];
    const float* bf    = (const float*)d_in[4];
    const float* Wt    = (const float*)d_in[5];
    const float* bt    = (const float*)d_in[6];
    const float* alpha = (const float*)d_in[7];
    float* out = (float*)d_out;

    const int BT = in_sizes[0] / D_DIM;    // 16384
    const int n_x = BT * D_DIM;            // 16777216
    const int n_w = E_DIM * D_DIM * D_DIM; // 8388608

    __half* xh_ptr = nullptr;
    __half* wh_ptr = nullptr;
    cudaGetSymbolAddress((void**)&xh_ptr, g_xh);
    cudaGetSymbolAddress((void**)&wh_ptr, g_wh);

    cudaFuncSetAttribute(moe_gate_h,
                         cudaFuncAttributeMaxDynamicSharedMemorySize, SMEM_BYTES);

    f2h_kernel<<<n_x / 1024, 256>>>(x, xh_ptr, n_x);
    f2h_kernel<<<n_w / 1024, 256>>>(Wg, wh_ptr, n_w);

    routing_kernel<<<(BT + 3) / 4, 128>>>(x, Wf, bf, Wt, bt, alpha, BT);

    dim3 grid(D_DIM / F_BN, BT / F_BM);   // (16, 128) = 2048 CTAs
    moe_gate_h<<<grid, N_THREADS, SMEM_BYTES>>>(bg, out);
}

// round 12
// speedup vs baseline: 1.7227x; 1.1697x over previous
#include <cuda_runtime.h>
#include <cuda_fp16.h>
#include <cstdint>
#include <math.h>

// Problem constants: B=8, T=2048, D=1024, E=8 -> BT=16384
#define D_DIM 1024
#define E_DIM 8
#define BT_MAX 16384

__device__ float g_mix[BT_MAX * E_DIM];
__device__ __half g_xh[BT_MAX * D_DIM];            // 32 MB fp16 copy of x
__device__ __half g_wh[E_DIM * D_DIM * D_DIM];     // 16 MB fp16 copy of Wg

// ===========================================================================
// PTX helpers
// ===========================================================================
__device__ __forceinline__ uint32_t smem_u32(const void* p) {
    uint32_t a;
    asm("{ .reg .u64 t; cvta.to.shared.u64 t, %1; cvt.u32.u64 %0, t; }" : "=r"(a) : "l"(p));
    return a;
}

#define CP_ASYNC16(dst, src) \
    asm volatile("cp.async.cg.shared.global [%0], [%1], 16;" :: "r"(dst), "l"(src) : "memory")

__device__ __forceinline__ void ldmatrix_x4(uint32_t* r, uint32_t addr) {
    asm volatile("ldmatrix.sync.aligned.m8n8.x4.shared.b16 {%0,%1,%2,%3}, [%4];"
        : "=r"(r[0]), "=r"(r[1]), "=r"(r[2]), "=r"(r[3]) : "r"(addr));
}

__device__ __forceinline__ void mma16n8k16h(float* d, const uint32_t* a, const uint32_t* b) {
    asm volatile("mma.sync.aligned.m16n8k16.row.col.f32.f16.f16.f32 "
        "{%0,%1,%2,%3}, {%4,%5,%6,%7}, {%8,%9}, {%0,%1,%2,%3};"
        : "+f"(d[0]), "+f"(d[1]), "+f"(d[2]), "+f"(d[3])
        : "r"(a[0]), "r"(a[1]), "r"(a[2]), "r"(a[3]), "r"(b[0]), "r"(b[1]));
}

// ===========================================================================
// Kernel 0: fp32 -> fp16 conversion
// ===========================================================================
__global__ __launch_bounds__(256) void f2h_kernel(const float* __restrict__ src,
                                                  __half* __restrict__ dst, int n)
{
    int i = (blockIdx.x * 256 + threadIdx.x) * 4;
    if (i < n) {
        float4 v = *(const float4*)(src + i);
        __half2 h0 = __floats2half2_rn(v.x, v.y);
        __half2 h1 = __floats2half2_rn(v.z, v.w);
        uint2 u;
        u.x = *(uint32_t*)&h0;
        u.y = *(uint32_t*)&h1;
        *(uint2*)(dst + i) = u;
    }
}

// ===========================================================================
// Kernel 1: routing (verified; fp32)
// ===========================================================================
__global__ __launch_bounds__(128) void routing_kernel(
    const float* __restrict__ x,
    const float* __restrict__ Wf, const float* __restrict__ bf,
    const float* __restrict__ Wt, const float* __restrict__ bt,
    const float* __restrict__ alpha, int BT)
{
    int warp = blockIdx.x * (blockDim.x >> 5) + (threadIdx.x >> 5);
    int lane = threadIdx.x & 31;
    if (warp >= BT) return;

    const float* xr = x + (size_t)warp * D_DIM;
    float xv[32];
#pragma unroll
    for (int j = 0; j < 32; ++j) xv[j] = xr[lane + 32 * j];

    float dots[16];
#pragma unroll
    for (int r = 0; r < 16; ++r) {
        const float* w = (r < 8) ? (Wt + r * D_DIM) : (Wf + (r - 8) * D_DIM);
        float s = 0.0f;
#pragma unroll
        for (int j = 0; j < 32; ++j) s += xv[j] * w[lane + 32 * j];
#pragma unroll
        for (int off = 16; off > 0; off >>= 1)
            s += __shfl_xor_sync(0xffffffffu, s, off);
        dots[r] = s;
    }

    float tl[8], fl[8];
#pragma unroll
    for (int e = 0; e < 8; ++e) { tl[e] = dots[e] + bt[e]; fl[e] = dots[8 + e] + bf[e]; }

    float v0 = tl[0]; int i0 = 0;
    float v1 = -INFINITY; int i1 = -1;
#pragma unroll
    for (int e = 1; e < 8; ++e) {
        if (tl[e] > v0) { v1 = v0; i1 = i0; v0 = tl[e]; i0 = e; }
        else if (tl[e] > v1) { v1 = tl[e]; i1 = e; }
    }
    float p1 = expf(v1 - v0);
    float sv0 = 1.0f / (1.0f + p1);
    float sv1 = p1 * sv0;

    float mf = fl[0];
#pragma unroll
    for (int e = 1; e < 8; ++e) mf = fmaxf(mf, fl[e]);
    float ef[8]; float se = 0.0f;
#pragma unroll
    for (int e = 0; e < 8; ++e) { ef[e] = expf(fl[e] - mf); se += ef[e]; }
    float inv_se = 1.0f / se;

    float a = 1.0f / (1.0f + expf(-alpha[0]));
    float one_m_a = 1.0f - a;

#pragma unroll
    for (int e = 0; e < 8; ++e) {
        float tp = (e == i0) ? sv0 : ((e == i1) ? sv1 : 0.0f);
        float m = a * tp + one_m_a * ef[e] * inv_se;
        if (lane == e) g_mix[(size_t)warp * E_DIM + e] = m;
    }
}

// ===========================================================================
// Kernel 2: fp16 mma.sync fused MoE gate, 256 threads, 2 CTAs/SM.
//   CTA tile 128(m) x 64(n); warp grid 4m x 2n; warp tile 32x32; m16n8k16.
//   BK=64; XOR-swizzled smem (128B rows, no padding); 4 stages; barrier and
//   wait only every 2 stages; flattened expert loop with register fold.
// ===========================================================================
#define F_BM 128
#define F_BN 64
#define F_BK 64
#define AST_B 16384u               // A stage bytes: 128 rows * 128 B
#define BST_B 8192u                // B stage bytes:  64 rows * 128 B
#define N_STAGES 4
#define KCH (D_DIM / F_BK)                // 16 k-chunks per expert
#define N_FLAT (E_DIM * KCH)              // 128
#define N_THREADS 256

// dynamic smem layout (bytes)
#define SMB_A    0                         // 4 * 16384 = 65536
#define SMB_B    65536                     // 4 *  8192 = 32768
#define SMB_MIX  98304                     // 4096 B
#define SMB_BGS  102400                    // 2048 B
#define SMEM_BYTES 104448

__global__ __launch_bounds__(N_THREADS, 2) void moe_gate_h(
    const float* __restrict__ bg,
    float* __restrict__ out)
{
    extern __shared__ char smc[];
    float* mixs = (float*)(smc + SMB_MIX);
    float* bgs  = (float*)(smc + SMB_BGS);

    const int tid = threadIdx.x;
    const int warp = tid >> 5, lane = tid & 31;
    const int wm = (warp & 3) * 32;       // 4 m-warps
    const int wn = (warp >> 2) * 32;      // 2 n-warps
    const int g = lane >> 2, tg = lane & 3;
    const int m0 = blockIdx.y * F_BM, n0 = blockIdx.x * F_BN;

    const uint32_t sAs = smem_u32(smc + SMB_A);
    const uint32_t sBs = smem_u32(smc + SMB_B);

    // ---- hoisted ldmatrix addressing (swizzled; byte offsets within a stage)
    // A: row = wm + (lane&15) (+16 per mf); col = kk*2 | hi*16, hi = lane>>4
    const uint32_t rowA = (uint32_t)(wm + (lane & 15));
    const uint32_t mA = (rowA & 7u) << 4;            // invariant under +16/+32
    const uint32_t cHiA = ((uint32_t)(lane >> 4)) << 4;
    const uint32_t aRowBase = rowA * 128u;
    // B: row = wn + (lane&7) + ((lane>>4)&1)*8 (+16 per pair); col = ((lane>>3)&1)*16
    const uint32_t rowB = (uint32_t)(wn + (lane & 7) + (((lane >> 4) & 1) << 3));
    const uint32_t mB = ((uint32_t)(lane & 7)) << 4;
    const uint32_t cLoB = ((uint32_t)((lane >> 3) & 1)) << 4;
    const uint32_t bRowBase = rowB * 128u;

    // ---- hoisted loader addressing: rows ldR (+32,+64,+96), 16B chunk ldQ
    const int ldR = tid >> 3, ldQ = tid & 7;          // ldR in [0,32)
    const uint32_t ldSwz = (uint32_t)(ldR * 128 + ((ldQ * 16) ^ ((ldR & 7) << 4)));
    const __half* ldA = g_xh + (size_t)(m0 + ldR) * D_DIM + ldQ * 8;
    const __half* ldB = g_wh + (size_t)(n0 + ldR) * D_DIM + ldQ * 8;

    // preload mix tile (128x8 f32 = 256 float4) and bg tiles (8x64 f32 = 128 float4)
    ((float4*)mixs)[tid] = ((const float4*)(g_mix + (size_t)m0 * E_DIM))[tid];
    if (tid < 128) {
        const int e = tid >> 4, c = (tid & 15) * 4;
        *(float4*)(bgs + e * F_BN + c) = *(const float4*)(bg + (size_t)e * D_DIM + n0 + c);
    }

    // one flat stage's loads: A 4 chunks + B 2 chunks per thread
#define H_LOAD_STAGE(flat) do {                                                      \
    const uint32_t _st = (uint32_t)(flat) & (N_STAGES - 1);                          \
    const uint32_t _aD = sAs + _st * AST_B + ldSwz;                                  \
    const uint32_t _bD = sBs + _st * BST_B + ldSwz;                                  \
    const int _k0 = ((flat) & (KCH - 1)) << 6;                                       \
    const __half* _a = ldA + _k0;                                                    \
    const __half* _b = ldB + ((size_t)((flat) >> 4) * (D_DIM * D_DIM)) + _k0;        \
    CP_ASYNC16(_aD,                  _a);                                            \
    CP_ASYNC16(_aD + 32u * 128u,     _a + 32 * D_DIM);                               \
    CP_ASYNC16(_aD + 64u * 128u,     _a + 64 * D_DIM);                               \
    CP_ASYNC16(_aD + 96u * 128u,     _a + 96 * D_DIM);                               \
    CP_ASYNC16(_bD,                  _b);                                            \
    CP_ASYNC16(_bD + 32u * 128u,     _b + 32 * D_DIM);                               \
} while (0)

    // prologue: stages 0..1
#pragma unroll
    for (int s = 0; s < 2; ++s) {
        H_LOAD_STAGE(s);
        asm volatile("cp.async.commit_group;" ::: "memory");
    }

    float accOut[2][4][4];
#pragma unroll
    for (int a = 0; a < 2; ++a)
#pragma unroll
        for (int b = 0; b < 4; ++b)
#pragma unroll
            for (int c = 0; c < 4; ++c) accOut[a][b][c] = 0.0f;

    float acc[2][4][4];
#pragma unroll
    for (int a = 0; a < 2; ++a)
#pragma unroll
        for (int b = 0; b < 4; ++b)
#pragma unroll
            for (int c = 0; c < 4; ++c) acc[a][b][c] = 0.0f;

    for (int flat = 0; flat < N_FLAT; ++flat) {
        // every 2 stages: full drain + barrier -> stages flat, flat+1 visible
        if ((flat & 1) == 0) {
            asm volatile("cp.async.wait_group 0;" ::: "memory");
            __syncthreads();
        }

        // prefetch stage flat+2 (buffer (flat+2)&3 was computed before the
        // last barrier by every warp -> safe to overwrite)
        if (flat + 2 < N_FLAT)
            H_LOAD_STAGE(flat + 2);
        asm volatile("cp.async.commit_group;" ::: "memory");

        // compute stage `flat`
        const uint32_t st = (uint32_t)flat & (N_STAGES - 1);
        const uint32_t aB = sAs + st * AST_B + aRowBase;
        const uint32_t bB = sBs + st * BST_B + bRowBase;
#pragma unroll
        for (int kk = 0; kk < F_BK; kk += 16) {
            const uint32_t kk2 = (uint32_t)(kk * 2);
            const uint32_t colA = (kk2 | cHiA) ^ mA;
            const uint32_t colB = (kk2 | cLoB) ^ mB;
            uint32_t afr[2][4], bfr[4][2];
#pragma unroll
            for (int mf = 0; mf < 2; ++mf)
                ldmatrix_x4(afr[mf], aB + (uint32_t)(mf * 2048) + colA);
#pragma unroll
            for (int pair = 0; pair < 2; ++pair) {
                uint32_t r[4];
                ldmatrix_x4(r, bB + (uint32_t)(pair * 2048) + colB);
                bfr[2 * pair][0] = r[0]; bfr[2 * pair][1] = r[1];
                bfr[2 * pair + 1][0] = r[2]; bfr[2 * pair + 1][1] = r[3];
            }
#pragma unroll
            for (int mf = 0; mf < 2; ++mf)
#pragma unroll
                for (int nf = 0; nf < 4; ++nf)
                    mma16n8k16h(acc[mf][nf], afr[mf], bfr[nf]);
        }

        // expert boundary (flat&15==15, odd -> no barrier interaction):
        // fold into accOut, reset acc
        if ((flat & (KCH - 1)) == KCH - 1) {
            const int e = flat >> 4;
#pragma unroll
            for (int mf = 0; mf < 2; ++mf) {
                const int r = wm + mf * 16 + g;
                const float mx0 = mixs[r * E_DIM + e];
                const float mx1 = mixs[(r + 8) * E_DIM + e];
#pragma unroll
                for (int nf = 0; nf < 4; ++nf) {
                    const int c = wn + nf * 8 + 2 * tg;
                    const float b0 = bgs[e * F_BN + c];
                    const float b1 = bgs[e * F_BN + c + 1];
                    accOut[mf][nf][0] += mx0 / (1.0f + __expf(-(acc[mf][nf][0] + b0)));
                    accOut[mf][nf][1] += mx0 / (1.0f + __expf(-(acc[mf][nf][1] + b1)));
                    accOut[mf][nf][2] += mx1 / (1.0f + __expf(-(acc[mf][nf][2] + b0)));
                    accOut[mf][nf][3] += mx1 / (1.0f + __expf(-(acc[mf][nf][3] + b1)));
                    acc[mf][nf][0] = 0.0f; acc[mf][nf][1] = 0.0f;
                    acc[mf][nf][2] = 0.0f; acc[mf][nf][3] = 0.0f;
                }
            }
        }
    }

    // write 128x64 tile (each warp: 32 rows x 32 cols)
#pragma unroll
    for (int mf = 0; mf < 2; ++mf) {
        const int r0 = m0 + wm + mf * 16 + g;
#pragma unroll
        for (int nf = 0; nf < 4; ++nf) {
            const int c = n0 + wn + nf * 8 + 2 * tg;
            *(float2*)(out + (size_t)r0 * D_DIM + c) =
                make_float2(accOut[mf][nf][0], accOut[mf][nf][1]);
            *(float2*)(out + (size_t)(r0 + 8) * D_DIM + c) =
                make_float2(accOut[mf][nf][2], accOut[mf][nf][3]);
        }
    }
}

// ===========================================================================
// Inputs: x, Wg, bg, Wf, bf, Wt, bt, alpha, num
// ===========================================================================
extern "C" void kernel_launch(void* const* d_in, const int* in_sizes, int n_in,
                              void* d_out, int out_size)
{
    const float* x     = (const float*)d_in[0];
    const float* Wg    = (const float*)d_in[1];
    const float* bg    = (const float*)d_in[2];
    const float* Wf    = (const float*)d_in[3];
    const float* bf    = (const float*)d_in[4];
    const float* Wt    = (const float*)d_in[5];
    const float* bt    = (const float*)d_in[6];
    const float* alpha = (const float*)d_in[7];
    float* out = (float*)d_out;

    const int BT = in_sizes[0] / D_DIM;    // 16384
    const int n_x = BT * D_DIM;            // 16777216
    const int n_w = E_DIM * D_DIM * D_DIM; // 8388608

    __half* xh_ptr = nullptr;
    __half* wh_ptr = nullptr;
    cudaGetSymbolAddress((void**)&xh_ptr, g_xh);
    cudaGetSymbolAddress((void**)&wh_ptr, g_wh);

    cudaFuncSetAttribute(moe_gate_h,
                         cudaFuncAttributeMaxDynamicSharedMemorySize, SMEM_BYTES);

    f2h_kernel<<<n_x / 1024, 256>>>(x, xh_ptr, n_x);
    f2h_kernel<<<n_w / 1024, 256>>>(Wg, wh_ptr, n_w);

    routing_kernel<<<(BT + 3) / 4, 128>>>(x, Wf, bf, Wt, bt, alpha, BT);

    dim3 grid(D_DIM / F_BN, BT / F_BM);   // (16, 128) = 2048 CTAs
    moe_gate_h<<<grid, N_THREADS, SMEM_BYTES>>>(bg, out);
}

// round 13
// speedup vs baseline: 1.9336x; 1.1224x over previous
#include <cuda_runtime.h>
#include <cuda_fp16.h>
#include <cstdint>
#include <math.h>

// Problem constants: B=8, T=2048, D=1024, E=8 -> BT=16384
#define D_DIM 1024
#define E_DIM 8
#define BT_MAX 16384

__device__ float g_mix[BT_MAX * E_DIM];
__device__ __half g_xh[BT_MAX * D_DIM];            // 32 MB fp16 copy of x
__device__ __half g_wh[E_DIM * D_DIM * D_DIM];     // 16 MB fp16 copy of Wg

// ===========================================================================
// PTX helpers
// ===========================================================================
__device__ __forceinline__ uint32_t smem_u32(const void* p) {
    uint32_t a;
    asm("{ .reg .u64 t; cvta.to.shared.u64 t, %1; cvt.u32.u64 %0, t; }" : "=r"(a) : "l"(p));
    return a;
}

#define CP_ASYNC16(dst, src) \
    asm volatile("cp.async.cg.shared.global [%0], [%1], 16;" :: "r"(dst), "l"(src) : "memory")

__device__ __forceinline__ void ldmatrix_x4(uint32_t* r, uint32_t addr) {
    asm volatile("ldmatrix.sync.aligned.m8n8.x4.shared.b16 {%0,%1,%2,%3}, [%4];"
        : "=r"(r[0]), "=r"(r[1]), "=r"(r[2]), "=r"(r[3]) : "r"(addr));
}

__device__ __forceinline__ void mma16n8k16h(float* d, const uint32_t* a, const uint32_t* b) {
    asm volatile("mma.sync.aligned.m16n8k16.row.col.f32.f16.f16.f32 "
        "{%0,%1,%2,%3}, {%4,%5,%6,%7}, {%8,%9}, {%0,%1,%2,%3};"
        : "+f"(d[0]), "+f"(d[1]), "+f"(d[2]), "+f"(d[3])
        : "r"(a[0]), "r"(a[1]), "r"(a[2]), "r"(a[3]), "r"(b[0]), "r"(b[1]));
}

// ===========================================================================
// Kernel 0: fp32 -> fp16 conversion
// ===========================================================================
__global__ __launch_bounds__(256) void f2h_kernel(const float* __restrict__ src,
                                                  __half* __restrict__ dst, int n)
{
    int i = (blockIdx.x * 256 + threadIdx.x) * 4;
    if (i < n) {
        float4 v = *(const float4*)(src + i);
        __half2 h0 = __floats2half2_rn(v.x, v.y);
        __half2 h1 = __floats2half2_rn(v.z, v.w);
        uint2 u;
        u.x = *(uint32_t*)&h0;
        u.y = *(uint32_t*)&h1;
        *(uint2*)(dst + i) = u;
    }
}

// ===========================================================================
// Kernel 1: routing (verified; fp32)
// ===========================================================================
__global__ __launch_bounds__(128) void routing_kernel(
    const float* __restrict__ x,
    const float* __restrict__ Wf, const float* __restrict__ bf,
    const float* __restrict__ Wt, const float* __restrict__ bt,
    const float* __restrict__ alpha, int BT)
{
    int warp = blockIdx.x * (blockDim.x >> 5) + (threadIdx.x >> 5);
    int lane = threadIdx.x & 31;
    if (warp >= BT) return;

    const float* xr = x + (size_t)warp * D_DIM;
    float xv[32];
#pragma unroll
    for (int j = 0; j < 32; ++j) xv[j] = xr[lane + 32 * j];

    float dots[16];
#pragma unroll
    for (int r = 0; r < 16; ++r) {
        const float* w = (r < 8) ? (Wt + r * D_DIM) : (Wf + (r - 8) * D_DIM);
        float s = 0.0f;
#pragma unroll
        for (int j = 0; j < 32; ++j) s += xv[j] * w[lane + 32 * j];
#pragma unroll
        for (int off = 16; off > 0; off >>= 1)
            s += __shfl_xor_sync(0xffffffffu, s, off);
        dots[r] = s;
    }

    float tl[8], fl[8];
#pragma unroll
    for (int e = 0; e < 8; ++e) { tl[e] = dots[e] + bt[e]; fl[e] = dots[8 + e] + bf[e]; }

    float v0 = tl[0]; int i0 = 0;
    float v1 = -INFINITY; int i1 = -1;
#pragma unroll
    for (int e = 1; e < 8; ++e) {
        if (tl[e] > v0) { v1 = v0; i1 = i0; v0 = tl[e]; i0 = e; }
        else if (tl[e] > v1) { v1 = tl[e]; i1 = e; }
    }
    float p1 = expf(v1 - v0);
    float sv0 = 1.0f / (1.0f + p1);
    float sv1 = p1 * sv0;

    float mf = fl[0];
#pragma unroll
    for (int e = 1; e < 8; ++e) mf = fmaxf(mf, fl[e]);
    float ef[8]; float se = 0.0f;
#pragma unroll
    for (int e = 0; e < 8; ++e) { ef[e] = expf(fl[e] - mf); se += ef[e]; }
    float inv_se = 1.0f / se;

    float a = 1.0f / (1.0f + expf(-alpha[0]));
    float one_m_a = 1.0f - a;

#pragma unroll
    for (int e = 0; e < 8; ++e) {
        float tp = (e == i0) ? sv0 : ((e == i1) ? sv1 : 0.0f);
        float m = a * tp + one_m_a * ef[e] * inv_se;
        if (lane == e) g_mix[(size_t)warp * E_DIM + e] = m;
    }
}

// ===========================================================================
// Kernel 2: fp16 mma.sync fused MoE gate, 256 threads, 2 CTAs/SM.
//   CTA tile 128(m) x 64(n); warp grid 4m x 2n; warp tile 32x32; m16n8k16.
//   BK=64; XOR-swizzled smem; 4 stages; barrier every 2 stages; flat loop
//   unrolled x4 with incremental prefetch pointers (no per-stage addr math).
// ===========================================================================
#define F_BM 128
#define F_BN 64
#define F_BK 64
#define AST_B 16384u               // A stage bytes: 128 rows * 128 B
#define BST_B 8192u                // B stage bytes:  64 rows * 128 B
#define N_STAGES 4
#define KCH (D_DIM / F_BK)                // 16 k-chunks per expert
#define N_FLAT (E_DIM * KCH)              // 128
#define N_THREADS 256

// dynamic smem layout (bytes)
#define SMB_A    0                         // 4 * 16384 = 65536
#define SMB_B    65536                     // 4 *  8192 = 32768
#define SMB_MIX  98304                     // 4096 B
#define SMB_BGS  102400                    // 2048 B
#define SMEM_BYTES 104448

__global__ __launch_bounds__(N_THREADS, 2) void moe_gate_h(
    const float* __restrict__ bg,
    float* __restrict__ out)
{
    extern __shared__ char smc[];
    float* mixs = (float*)(smc + SMB_MIX);
    float* bgs  = (float*)(smc + SMB_BGS);

    const int tid = threadIdx.x;
    const int warp = tid >> 5, lane = tid & 31;
    const int wm = (warp & 3) * 32;       // 4 m-warps
    const int wn = (warp >> 2) * 32;      // 2 n-warps
    const int g = lane >> 2, tg = lane & 3;
    const int m0 = blockIdx.y * F_BM, n0 = blockIdx.x * F_BN;

    const uint32_t sAs = smem_u32(smc + SMB_A);
    const uint32_t sBs = smem_u32(smc + SMB_B);

    // ---- hoisted ldmatrix addressing (swizzled; byte offsets within a stage)
    const uint32_t rowA = (uint32_t)(wm + (lane & 15));
    const uint32_t mA = (rowA & 7u) << 4;
    const uint32_t cHiA = ((uint32_t)(lane >> 4)) << 4;
    const uint32_t aRowBase = rowA * 128u;
    const uint32_t rowB = (uint32_t)(wn + (lane & 7) + (((lane >> 4) & 1) << 3));
    const uint32_t mB = ((uint32_t)(lane & 7)) << 4;
    const uint32_t cLoB = ((uint32_t)((lane >> 3) & 1)) << 4;
    const uint32_t bRowBase = rowB * 128u;

    // hoisted swizzled column offsets per kk (loop-invariant)
    uint32_t colA[4], colB[4];
#pragma unroll
    for (int kki = 0; kki < 4; ++kki) {
        const uint32_t kk2 = (uint32_t)(kki * 32);
        colA[kki] = (kk2 | cHiA) ^ mA;
        colB[kki] = (kk2 | cLoB) ^ mB;
    }

    // ---- hoisted loader addressing: rows ldR (+32,+64,+96), 16B chunk ldQ
    const int ldR = tid >> 3, ldQ = tid & 7;          // ldR in [0,32)
    const uint32_t ldSwz = (uint32_t)(ldR * 128 + ((ldQ * 16) ^ ((ldR & 7) << 4)));
    const __half* ldA = g_xh + (size_t)(m0 + ldR) * D_DIM + ldQ * 8;
    const __half* ldB = g_wh + (size_t)(n0 + ldR) * D_DIM + ldQ * 8;

    // preload mix tile and bg tiles
    ((float4*)mixs)[tid] = ((const float4*)(g_mix + (size_t)m0 * E_DIM))[tid];
    if (tid < 128) {
        const int e = tid >> 4, c = (tid & 15) * 4;
        *(float4*)(bgs + e * F_BN + c) = *(const float4*)(bg + (size_t)e * D_DIM + n0 + c);
    }

    // issue loads for one stage into buffer st from pointers a,b
#define H_ISSUE(stConst, a, b) do {                                                  \
    const uint32_t _aD = sAs + (stConst) * AST_B + ldSwz;                            \
    const uint32_t _bD = sBs + (stConst) * BST_B + ldSwz;                            \
    CP_ASYNC16(_aD,              (a));                                               \
    CP_ASYNC16(_aD + 32u * 128u, (a) + 32 * D_DIM);                                  \
    CP_ASYNC16(_aD + 64u * 128u, (a) + 64 * D_DIM);                                  \
    CP_ASYNC16(_aD + 96u * 128u, (a) + 96 * D_DIM);                                  \
    CP_ASYNC16(_bD,              (b));                                               \
    CP_ASYNC16(_bD + 32u * 128u, (b) + 32 * D_DIM);                                  \
} while (0)

    // compute one stage from buffer stConst into acc
#define H_COMPUTE(stConst) do {                                                      \
    const uint32_t aB = sAs + (stConst) * AST_B + aRowBase;                          \
    const uint32_t bB = sBs + (stConst) * BST_B + bRowBase;                          \
    _Pragma("unroll")                                                                \
    for (int kki = 0; kki < 4; ++kki) {                                              \
        uint32_t afr[2][4], bfr[4][2];                                               \
        ldmatrix_x4(afr[0], aB + colA[kki]);                                         \
        ldmatrix_x4(afr[1], aB + 2048u + colA[kki]);                                 \
        {                                                                            \
            uint32_t r[4];                                                           \
            ldmatrix_x4(r, bB + colB[kki]);                                          \
            bfr[0][0] = r[0]; bfr[0][1] = r[1]; bfr[1][0] = r[2]; bfr[1][1] = r[3];  \
            ldmatrix_x4(r, bB + 2048u + colB[kki]);                                  \
            bfr[2][0] = r[0]; bfr[2][1] = r[1]; bfr[3][0] = r[2]; bfr[3][1] = r[3];  \
        }                                                                            \
        _Pragma("unroll")                                                            \
        for (int mf = 0; mf < 2; ++mf)                                               \
            _Pragma("unroll")                                                        \
            for (int nf = 0; nf < 4; ++nf)                                           \
                mma16n8k16h(acc[mf][nf], afr[mf], bfr[nf]);                          \
    }                                                                                \
} while (0)

#define H_FOLD(eVal) do {                                                            \
    const int _e = (eVal);                                                           \
    _Pragma("unroll")                                                                \
    for (int mf = 0; mf < 2; ++mf) {                                                 \
        const int r = wm + mf * 16 + g;                                              \
        const float mx0 = mixs[r * E_DIM + _e];                                      \
        const float mx1 = mixs[(r + 8) * E_DIM + _e];                                \
        _Pragma("unroll")                                                            \
        for (int nf = 0; nf < 4; ++nf) {                                             \
            const int c = wn + nf * 8 + 2 * tg;                                      \
            const float b0 = bgs[_e * F_BN + c];                                     \
            const float b1 = bgs[_e * F_BN + c + 1];                                 \
            accOut[mf][nf][0] += mx0 / (1.0f + __expf(-(acc[mf][nf][0] + b0)));      \
            accOut[mf][nf][1] += mx0 / (1.0f + __expf(-(acc[mf][nf][1] + b1)));      \
            accOut[mf][nf][2] += mx1 / (1.0f + __expf(-(acc[mf][nf][2] + b0)));      \
            accOut[mf][nf][3] += mx1 / (1.0f + __expf(-(acc[mf][nf][3] + b1)));      \
            acc[mf][nf][0] = 0.0f; acc[mf][nf][1] = 0.0f;                            \
            acc[mf][nf][2] = 0.0f; acc[mf][nf][3] = 0.0f;                            \
        }                                                                            \
    }                                                                                \
} while (0)

    // prologue: stages 0 (k0=0), 1 (k0=64), expert 0
    H_ISSUE(0u, ldA, ldB);
    asm volatile("cp.async.commit_group;" ::: "memory");
    H_ISSUE(1u, ldA + 64, ldB + 64);
    asm volatile("cp.async.commit_group;" ::: "memory");

    // incremental prefetch pointers (next prefetch stage = 2: k-chunk 2, expert 0)
    const __half* pfA = ldA + 128;
    const __half* pfB = ldB + 128;
    int pfK = 2;

    float accOut[2][4][4];
#pragma unroll
    for (int a = 0; a < 2; ++a)
#pragma unroll
        for (int b = 0; b < 4; ++b)
#pragma unroll
            for (int c = 0; c < 4; ++c) accOut[a][b][c] = 0.0f;

    float acc[2][4][4];
#pragma unroll
    for (int a = 0; a < 2; ++a)
#pragma unroll
        for (int b = 0; b < 4; ++b)
#pragma unroll
            for (int c = 0; c < 4; ++c) acc[a][b][c] = 0.0f;

    // main body: flat = f4+u, f4 in [0,124); buffer index == u, prefetch buf == (u+2)&3
    for (int f4 = 0; f4 < N_FLAT - 4; f4 += 4) {
#pragma unroll
        for (int u = 0; u < 4; ++u) {
            if ((u & 1) == 0) {
                asm volatile("cp.async.wait_group 0;" ::: "memory");
                __syncthreads();
            }
            H_ISSUE((uint32_t)((u + 2) & 3), pfA, pfB);
            asm volatile("cp.async.commit_group;" ::: "memory");
            pfA += 64; pfB += 64;
            if (++pfK == KCH) { pfK = 0; pfA -= 1024; pfB += (D_DIM * D_DIM - 1024); }
            H_COMPUTE((uint32_t)u);
            if (u == 3 && ((f4 & 12) == 12))
                H_FOLD((f4 + 3) >> 4);
        }
    }

    // tail: flat = 124..127 (prefetch only for 126,127)
    {
        const int f4 = N_FLAT - 4;
#pragma unroll
        for (int u = 0; u < 4; ++u) {
            if ((u & 1) == 0) {
                asm volatile("cp.async.wait_group 0;" ::: "memory");
                __syncthreads();
            }
            if (u < 2) {
                H_ISSUE((uint32_t)((u + 2) & 3), pfA, pfB);
                pfA += 64; pfB += 64;
            }
            asm volatile("cp.async.commit_group;" ::: "memory");
            H_COMPUTE((uint32_t)u);
            if (u == 3)
                H_FOLD((f4 + 3) >> 4);
        }
    }

    // write 128x64 tile (each warp: 32 rows x 32 cols)
#pragma unroll
    for (int mf = 0; mf < 2; ++mf) {
        const int r0 = m0 + wm + mf * 16 + g;
#pragma unroll
        for (int nf = 0; nf < 4; ++nf) {
            const int c = n0 + wn + nf * 8 + 2 * tg;
            *(float2*)(out + (size_t)r0 * D_DIM + c) =
                make_float2(accOut[mf][nf][0], accOut[mf][nf][1]);
            *(float2*)(out + (size_t)(r0 + 8) * D_DIM + c) =
                make_float2(accOut[mf][nf][2], accOut[mf][nf][3]);
        }
    }
}

// ===========================================================================
// Inputs: x, Wg, bg, Wf, bf, Wt, bt, alpha, num
// ===========================================================================
extern "C" void kernel_launch(void* const* d_in, const int* in_sizes, int n_in,
                              void* d_out, int out_size)
{
    const float* x     = (const float*)d_in[0];
    const float* Wg    = (const float*)d_in[1];
    const float* bg    = (const float*)d_in[2];
    const float* Wf    = (const float*)d_in[3];
    const float* bf    = (const float*)d_in[4];
    const float* Wt    = (const float*)d_in[5];
    const float* bt    = (const float*)d_in[6];
    const float* alpha = (const float*)d_in[7];
    float* out = (float*)d_out;

    const int BT = in_sizes[0] / D_DIM;    // 16384
    const int n_x = BT * D_DIM;            // 16777216
    const int n_w = E_DIM * D_DIM * D_DIM; // 8388608

    __half* xh_ptr = nullptr;
    __half* wh_ptr = nullptr;
    cudaGetSymbolAddress((void**)&xh_ptr, g_xh);
    cudaGetSymbolAddress((void**)&wh_ptr, g_wh);

    cudaFuncSetAttribute(moe_gate_h,
                         cudaFuncAttributeMaxDynamicSharedMemorySize, SMEM_BYTES);

    f2h_kernel<<<n_x / 1024, 256>>>(x, xh_ptr, n_x);
    f2h_kernel<<<n_w / 1024, 256>>>(Wg, wh_ptr, n_w);

    routing_kernel<<<(BT + 3) / 4, 128>>>(x, Wf, bf, Wt, bt, alpha, BT);

    dim3 grid(D_DIM / F_BN, BT / F_BM);   // (16, 128) = 2048 CTAs
    moe_gate_h<<<grid, N_THREADS, SMEM_BYTES>>>(bg, out);
}

// round 14
// speedup vs baseline: 1.9861x; 1.0272x over previous
#include <cuda_runtime.h>
#include <cuda_fp16.h>
#include <cstdint>
#include <math.h>

// Problem constants: B=8, T=2048, D=1024, E=8 -> BT=16384
#define D_DIM 1024
#define E_DIM 8
#define BT_MAX 16384

__device__ float g_mix[BT_MAX * E_DIM];
__device__ __half g_xh[BT_MAX * D_DIM];            // 32 MB fp16 copy of x
__device__ __half g_wh[E_DIM * D_DIM * D_DIM];     // 16 MB fp16 copy of Wg

// ===========================================================================
// PTX helpers
// ===========================================================================
__device__ __forceinline__ uint32_t smem_u32(const void* p) {
    uint32_t a;
    asm("{ .reg .u64 t; cvta.to.shared.u64 t, %1; cvt.u32.u64 %0, t; }" : "=r"(a) : "l"(p));
    return a;
}

#define CP_ASYNC16(dst, src) \
    asm volatile("cp.async.cg.shared.global [%0], [%1], 16;" :: "r"(dst), "l"(src) : "memory")

#define CP_ASYNC_ARRIVE_NOINC(mbar) \
    asm volatile("cp.async.mbarrier.arrive.noinc.shared::cta.b64 [%0];" :: "r"(mbar) : "memory")

#define MBARRIER_INIT(addr, cnt) \
    asm volatile("mbarrier.init.shared.b64 [%0], %1;" :: "r"(addr), "r"(cnt) : "memory")

#define MBARRIER_ARRIVE(addr) \
    asm volatile("mbarrier.arrive.shared.b64 _, [%0];" :: "r"(addr) : "memory")

#define MBARRIER_WAIT_PARITY(addr, ph) do {                                      \
    uint32_t _m = (addr); uint32_t _p = (ph); uint32_t _d;                       \
    asm volatile("{\n\t.reg .pred p;\n\t"                                        \
        "mbarrier.try_wait.parity.acquire.cta.shared::cta.b64 p, [%1], %2;\n\t"  \
        "selp.b32 %0, 1, 0, p;\n\t}"                                             \
        : "=r"(_d) : "r"(_m), "r"(_p) : "memory");                               \
    if (!_d) {                                                                   \
        asm volatile("{\n\t.reg .pred P1;\n\t"                                   \
        "W%=:\n\t"                                                               \
        "mbarrier.try_wait.parity.acquire.cta.shared::cta.b64 P1, [%0], %1, 0x989680;\n\t" \
        "@P1 bra.uni DN%=;\n\t"                                                  \
        "bra.uni W%=;\n\t"                                                       \
        "DN%=:\n\t}" :: "r"(_m), "r"(_p) : "memory");                            \
    } } while (0)

__device__ __forceinline__ void ldmatrix_x4(uint32_t* r, uint32_t addr) {
    asm volatile("ldmatrix.sync.aligned.m8n8.x4.shared.b16 {%0,%1,%2,%3}, [%4];"
        : "=r"(r[0]), "=r"(r[1]), "=r"(r[2]), "=r"(r[3]) : "r"(addr));
}

__device__ __forceinline__ void mma16n8k16h(float* d, const uint32_t* a, const uint32_t* b) {
    asm volatile("mma.sync.aligned.m16n8k16.row.col.f32.f16.f16.f32 "
        "{%0,%1,%2,%3}, {%4,%5,%6,%7}, {%8,%9}, {%0,%1,%2,%3};"
        : "+f"(d[0]), "+f"(d[1]), "+f"(d[2]), "+f"(d[3])
        : "r"(a[0]), "r"(a[1]), "r"(a[2]), "r"(a[3]), "r"(b[0]), "r"(b[1]));
}

// ===========================================================================
// Kernel 0: fp32 -> fp16 conversion
// ===========================================================================
__global__ __launch_bounds__(256) void f2h_kernel(const float* __restrict__ src,
                                                  __half* __restrict__ dst, int n)
{
    int i = (blockIdx.x * 256 + threadIdx.x) * 4;
    if (i < n) {
        float4 v = *(const float4*)(src + i);
        __half2 h0 = __floats2half2_rn(v.x, v.y);
        __half2 h1 = __floats2half2_rn(v.z, v.w);
        uint2 u;
        u.x = *(uint32_t*)&h0;
        u.y = *(uint32_t*)&h1;
        *(uint2*)(dst + i) = u;
    }
}

// ===========================================================================
// Kernel 1: routing (verified; fp32)
// ===========================================================================
__global__ __launch_bounds__(128) void routing_kernel(
    const float* __restrict__ x,
    const float* __restrict__ Wf, const float* __restrict__ bf,
    const float* __restrict__ Wt, const float* __restrict__ bt,
    const float* __restrict__ alpha, int BT)
{
    int warp = blockIdx.x * (blockDim.x >> 5) + (threadIdx.x >> 5);
    int lane = threadIdx.x & 31;
    if (warp >= BT) return;

    const float* xr = x + (size_t)warp * D_DIM;
    float xv[32];
#pragma unroll
    for (int j = 0; j < 32; ++j) xv[j] = xr[lane + 32 * j];

    float dots[16];
#pragma unroll
    for (int r = 0; r < 16; ++r) {
        const float* w = (r < 8) ? (Wt + r * D_DIM) : (Wf + (r - 8) * D_DIM);
        float s = 0.0f;
#pragma unroll
        for (int j = 0; j < 32; ++j) s += xv[j] * w[lane + 32 * j];
#pragma unroll
        for (int off = 16; off > 0; off >>= 1)
            s += __shfl_xor_sync(0xffffffffu, s, off);
        dots[r] = s;
    }

    float tl[8], fl[8];
#pragma unroll
    for (int e = 0; e < 8; ++e) { tl[e] = dots[e] + bt[e]; fl[e] = dots[8 + e] + bf[e]; }

    float v0 = tl[0]; int i0 = 0;
    float v1 = -INFINITY; int i1 = -1;
#pragma unroll
    for (int e = 1; e < 8; ++e) {
        if (tl[e] > v0) { v1 = v0; i1 = i0; v0 = tl[e]; i0 = e; }
        else if (tl[e] > v1) { v1 = tl[e]; i1 = e; }
    }
    float p1 = expf(v1 - v0);
    float sv0 = 1.0f / (1.0f + p1);
    float sv1 = p1 * sv0;

    float mf = fl[0];
#pragma unroll
    for (int e = 1; e < 8; ++e) mf = fmaxf(mf, fl[e]);
    float ef[8]; float se = 0.0f;
#pragma unroll
    for (int e = 0; e < 8; ++e) { ef[e] = expf(fl[e] - mf); se += ef[e]; }
    float inv_se = 1.0f / se;

    float a = 1.0f / (1.0f + expf(-alpha[0]));
    float one_m_a = 1.0f - a;

#pragma unroll
    for (int e = 0; e < 8; ++e) {
        float tp = (e == i0) ? sv0 : ((e == i1) ? sv1 : 0.0f);
        float m = a * tp + one_m_a * ef[e] * inv_se;
        if (lane == e) g_mix[(size_t)warp * E_DIM + e] = m;
    }
}

// ===========================================================================
// Kernel 2: fp16 mma.sync fused MoE gate, 256 threads, 2 CTAs/SM.
//   CTA tile 128(m) x 64(n); warp grid 4m x 2n; warp tile 32x32; m16n8k16.
//   BK=64; XOR-swizzled smem; 4 stage buffers; mbarrier producer/consumer
//   pipeline (no block barrier in mainloop); incremental prefetch pointers.
// ===========================================================================
#define F_BM 128
#define F_BN 64
#define F_BK 64
#define AST_B 16384u               // A stage bytes: 128 rows * 128 B
#define BST_B 8192u                // B stage bytes:  64 rows * 128 B
#define N_STAGES 4
#define KCH (D_DIM / F_BK)                // 16 k-chunks per expert
#define N_FLAT (E_DIM * KCH)              // 128
#define N_THREADS 256

// dynamic smem layout (bytes)
#define SMB_A    0                         // 4 * 16384 = 65536
#define SMB_B    65536                     // 4 *  8192 = 32768
#define SMB_MIX  98304                     // 4096 B
#define SMB_BGS  102400                    // 2048 B
#define SMB_BAR  104448                    // 8 mbarriers * 8 B = 64 B
#define SMEM_BYTES 104512

__global__ __launch_bounds__(N_THREADS, 2) void moe_gate_h(
    const float* __restrict__ bg,
    float* __restrict__ out)
{
    extern __shared__ char smc[];
    float* mixs = (float*)(smc + SMB_MIX);
    float* bgs  = (float*)(smc + SMB_BGS);

    const int tid = threadIdx.x;
    const int warp = tid >> 5, lane = tid & 31;
    const int wm = (warp & 3) * 32;       // 4 m-warps
    const int wn = (warp >> 2) * 32;      // 2 n-warps
    const int g = lane >> 2, tg = lane & 3;
    const int m0 = blockIdx.y * F_BM, n0 = blockIdx.x * F_BN;

    const uint32_t sAs = smem_u32(smc + SMB_A);
    const uint32_t sBs = smem_u32(smc + SMB_B);
    const uint32_t sBar = smem_u32(smc + SMB_BAR);
    // full[s] = sBar + s*8 ; empty[s] = sBar + 32 + s*8

    // ---- hoisted ldmatrix addressing (swizzled; byte offsets within a stage)
    const uint32_t rowA = (uint32_t)(wm + (lane & 15));
    const uint32_t mA = (rowA & 7u) << 4;
    const uint32_t cHiA = ((uint32_t)(lane >> 4)) << 4;
    const uint32_t aRowBase = rowA * 128u;
    const uint32_t rowB = (uint32_t)(wn + (lane & 7) + (((lane >> 4) & 1) << 3));
    const uint32_t mB = ((uint32_t)(lane & 7)) << 4;
    const uint32_t cLoB = ((uint32_t)((lane >> 3) & 1)) << 4;
    const uint32_t bRowBase = rowB * 128u;

    uint32_t colA[4], colB[4];
#pragma unroll
    for (int kki = 0; kki < 4; ++kki) {
        const uint32_t kk2 = (uint32_t)(kki * 32);
        colA[kki] = (kk2 | cHiA) ^ mA;
        colB[kki] = (kk2 | cLoB) ^ mB;
    }

    // ---- hoisted loader addressing: rows ldR (+32,+64,+96), 16B chunk ldQ
    const int ldR = tid >> 3, ldQ = tid & 7;          // ldR in [0,32)
    const uint32_t ldSwz = (uint32_t)(ldR * 128 + ((ldQ * 16) ^ ((ldR & 7) << 4)));
    const __half* ldA = g_xh + (size_t)(m0 + ldR) * D_DIM + ldQ * 8;
    const __half* ldB = g_wh + (size_t)(n0 + ldR) * D_DIM + ldQ * 8;

    // init barriers + preload mix/bg tiles
    if (tid == 0) {
#pragma unroll
        for (int s = 0; s < 4; ++s) {
            MBARRIER_INIT(sBar + s * 8, N_THREADS);   // full[s]
            MBARRIER_INIT(sBar + 32 + s * 8, 8);      // empty[s], 1 arrive/warp
        }
    }
    ((float4*)mixs)[tid] = ((const float4*)(g_mix + (size_t)m0 * E_DIM))[tid];
    if (tid < 128) {
        const int e = tid >> 4, c = (tid & 15) * 4;
        *(float4*)(bgs + e * F_BN + c) = *(const float4*)(bg + (size_t)e * D_DIM + n0 + c);
    }
    __syncthreads();

#define H_ISSUE(st, a, b) do {                                                       \
    const uint32_t _aD = sAs + (uint32_t)(st) * AST_B + ldSwz;                       \
    const uint32_t _bD = sBs + (uint32_t)(st) * BST_B + ldSwz;                       \
    CP_ASYNC16(_aD,              (a));                                               \
    CP_ASYNC16(_aD + 32u * 128u, (a) + 32 * D_DIM);                                  \
    CP_ASYNC16(_aD + 64u * 128u, (a) + 64 * D_DIM);                                  \
    CP_ASYNC16(_aD + 96u * 128u, (a) + 96 * D_DIM);                                  \
    CP_ASYNC16(_bD,              (b));                                               \
    CP_ASYNC16(_bD + 32u * 128u, (b) + 32 * D_DIM);                                  \
    CP_ASYNC_ARRIVE_NOINC(sBar + (uint32_t)(st) * 8u);                               \
} while (0)

#define H_COMPUTE(st) do {                                                           \
    const uint32_t aB = sAs + (uint32_t)(st) * AST_B + aRowBase;                     \
    const uint32_t bB = sBs + (uint32_t)(st) * BST_B + bRowBase;                     \
    _Pragma("unroll")                                                                \
    for (int kki = 0; kki < 4; ++kki) {                                              \
        uint32_t afr[2][4], bfr[4][2];                                               \
        ldmatrix_x4(afr[0], aB + colA[kki]);                                         \
        ldmatrix_x4(afr[1], aB + 2048u + colA[kki]);                                 \
        {                                                                            \
            uint32_t r[4];                                                           \
            ldmatrix_x4(r, bB + colB[kki]);                                          \
            bfr[0][0] = r[0]; bfr[0][1] = r[1]; bfr[1][0] = r[2]; bfr[1][1] = r[3];  \
            ldmatrix_x4(r, bB + 2048u + colB[kki]);                                  \
            bfr[2][0] = r[0]; bfr[2][1] = r[1]; bfr[3][0] = r[2]; bfr[3][1] = r[3];  \
        }                                                                            \
        _Pragma("unroll")                                                            \
        for (int mf = 0; mf < 2; ++mf)                                               \
            _Pragma("unroll")                                                        \
            for (int nf = 0; nf < 4; ++nf)                                           \
                mma16n8k16h(acc[mf][nf], afr[mf], bfr[nf]);                          \
    }                                                                                \
} while (0)

#define H_FOLD(eVal) do {                                                            \
    const int _e = (eVal);                                                           \
    _Pragma("unroll")                                                                \
    for (int mf = 0; mf < 2; ++mf) {                                                 \
        const int r = wm + mf * 16 + g;                                              \
        const float mx0 = mixs[r * E_DIM + _e];                                      \
        const float mx1 = mixs[(r + 8) * E_DIM + _e];                                \
        _Pragma("unroll")                                                            \
        for (int nf = 0; nf < 4; ++nf) {                                             \
            const int c = wn + nf * 8 + 2 * tg;                                      \
            const float b0 = bgs[_e * F_BN + c];                                     \
            const float b1 = bgs[_e * F_BN + c + 1];                                 \
            accOut[mf][nf][0] += mx0 / (1.0f + __expf(-(acc[mf][nf][0] + b0)));      \
            accOut[mf][nf][1] += mx0 / (1.0f + __expf(-(acc[mf][nf][1] + b1)));      \
            accOut[mf][nf][2] += mx1 / (1.0f + __expf(-(acc[mf][nf][2] + b0)));      \
            accOut[mf][nf][3] += mx1 / (1.0f + __expf(-(acc[mf][nf][3] + b1)));      \
            acc[mf][nf][0] = 0.0f; acc[mf][nf][1] = 0.0f;                            \
            acc[mf][nf][2] = 0.0f; acc[mf][nf][3] = 0.0f;                            \
        }                                                                            \
    }                                                                                \
} while (0)

    // prologue: fill stages 0,1 (buffers 0,1; first use, no empty wait)
    H_ISSUE(0, ldA, ldB);
    H_ISSUE(1, ldA + 64, ldB + 64);

    // incremental prefetch pointers (next fill = stage 2: k-chunk 2, expert 0)
    const __half* pfA = ldA + 128;
    const __half* pfB = ldB + 128;
    int pfK = 2;

    float accOut[2][4][4];
#pragma unroll
    for (int a = 0; a < 2; ++a)
#pragma unroll
        for (int b = 0; b < 4; ++b)
#pragma unroll
            for (int c = 0; c < 4; ++c) accOut[a][b][c] = 0.0f;

    float acc[2][4][4];
#pragma unroll
    for (int a = 0; a < 2; ++a)
#pragma unroll
        for (int b = 0; b < 4; ++b)
#pragma unroll
            for (int c = 0; c < 4; ++c) acc[a][b][c] = 0.0f;

    // mainloop: consume stage t, fill stage t+2 (prefetch distance 2)
#pragma unroll 4
    for (int t = 0; t < N_FLAT; ++t) {
        const int u = t + 2;
        if (u < N_FLAT) {
            if (u >= N_STAGES) {
                // buffer (u&3) free once all warps consumed stage u-4
                MBARRIER_WAIT_PARITY(sBar + 32u + (uint32_t)(u & 3) * 8u,
                                     (uint32_t)(((u >> 2) - 1) & 1));
            }
            H_ISSUE(u & 3, pfA, pfB);
            pfA += 64; pfB += 64;
            if (++pfK == KCH) { pfK = 0; pfA -= 1024; pfB += (D_DIM * D_DIM - 1024); }
        }

        // wait stage t data (full barrier flipped (t>>2)+1 times)
        MBARRIER_WAIT_PARITY(sBar + (uint32_t)(t & 3) * 8u, (uint32_t)((t >> 2) & 1));
        H_COMPUTE(t & 3);
        if (lane == 0) MBARRIER_ARRIVE(sBar + 32u + (uint32_t)(t & 3) * 8u);

        if ((t & (KCH - 1)) == KCH - 1)
            H_FOLD(t >> 4);
    }

    // write 128x64 tile (each warp: 32 rows x 32 cols)
#pragma unroll
    for (int mf = 0; mf < 2; ++mf) {
        const int r0 = m0 + wm + mf * 16 + g;
#pragma unroll
        for (int nf = 0; nf < 4; ++nf) {
            const int c = n0 + wn + nf * 8 + 2 * tg;
            *(float2*)(out + (size_t)r0 * D_DIM + c) =
                make_float2(accOut[mf][nf][0], accOut[mf][nf][1]);
            *(float2*)(out + (size_t)(r0 + 8) * D_DIM + c) =
                make_float2(accOut[mf][nf][2], accOut[mf][nf][3]);
        }
    }
}

// ===========================================================================
// Inputs: x, Wg, bg, Wf, bf, Wt, bt, alpha, num
// ===========================================================================
extern "C" void kernel_launch(void* const* d_in, const int* in_sizes, int n_in,
                              void* d_out, int out_size)
{
    const float* x     = (const float*)d_in[0];
    const float* Wg    = (const float*)d_in[1];
    const float* bg    = (const float*)d_in[2];
    const float* Wf    = (const float*)d_in[3];
    const float* bf    = (const float*)d_in[4];
    const float* Wt    = (const float*)d_in[5];
    const float* bt    = (const float*)d_in[6];
    const float* alpha = (const float*)d_in[7];
    float* out = (float*)d_out;

    const int BT = in_sizes[0] / D_DIM;    // 16384
    const int n_x = BT * D_DIM;            // 16777216
    const int n_w = E_DIM * D_DIM * D_DIM; // 8388608

    __half* xh_ptr = nullptr;
    __half* wh_ptr = nullptr;
    cudaGetSymbolAddress((void**)&xh_ptr, g_xh);
    cudaGetSymbolAddress((void**)&wh_ptr, g_wh);

    cudaFuncSetAttribute(moe_gate_h,
                         cudaFuncAttributeMaxDynamicSharedMemorySize, SMEM_BYTES);

    f2h_kernel<<<n_x / 1024, 256>>>(x, xh_ptr, n_x);
    f2h_kernel<<<n_w / 1024, 256>>>(Wg, wh_ptr, n_w);

    routing_kernel<<<(BT + 3) / 4, 128>>>(x, Wf, bf, Wt, bt, alpha, BT);

    dim3 grid(D_DIM / F_BN, BT / F_BM);   // (16, 128) = 2048 CTAs
    moe_gate_h<<<grid, N_THREADS, SMEM_BYTES>>>(bg, out);
}